// round 1
// baseline (speedup 1.0000x reference)
#include <cuda_runtime.h>
#include <math.h>

#define VOCAB 32768
#define D 512
#define NB 3
#define NF 3
#define T 4
#define NJ 36   // T*NF*NB

// ---------------- scratch (device globals; no allocation) ----------------
__device__ float g_memory[NF*NB*D];
__device__ float g_xin[NF*D];
__device__ float g_decay[NF];
__device__ float g_part[NF*NB*8*D];
__device__ float g_U[NJ*D];          // [t][f][n][d], j = t*9+f*3+n
__device__ float g_w[NJ];            // bubble weights [t][f][n]
__device__ float g_P[2*NJ*VOCAB];    // two d-halves: [half][j][v]
__device__ float g_red5[T*64*12];
__device__ float g_c[NJ];            // meta coeffs c = weights_f * w_fn
__device__ float g_invSf[T*NF];
__device__ float g_Srho[T];
__device__ float g_red7[T*64*2];
__device__ float g_invStok[T];

// ---------------- helpers ----------------
__device__ __forceinline__ float blockReduceSum512(float v, float* sh) {
    #pragma unroll
    for (int o = 16; o > 0; o >>= 1) v += __shfl_down_sync(0xffffffffu, v, o);
    int lane = threadIdx.x & 31, wid = threadIdx.x >> 5;
    if (lane == 0) sh[wid] = v;
    __syncthreads();
    float r;
    if (wid == 0) {
        r = (lane < 16) ? sh[lane] : 0.f;
        #pragma unroll
        for (int o = 8; o > 0; o >>= 1) r += __shfl_down_sync(0xffffffffu, r, o);
        if (lane == 0) sh[0] = r;
    }
    __syncthreads();
    r = sh[0];
    __syncthreads();
    return r;
}

// ---------------- phase 1: foam recurrence ----------------
__global__ void k_init(const int* __restrict__ tokens, const float* __restrict__ E,
                       const float* __restrict__ mdb, const float* __restrict__ nsens) {
    int f = blockIdx.x, e = threadIdx.x;
    #pragma unroll
    for (int n = 0; n < NB; n++) g_memory[(f*NB+n)*D + e] = 0.f;
    float x = E[(size_t)tokens[0]*D + e];
    g_xin[f*D + e] = x;  // decay * mem_mean == 0
    if (e == 0) {
        float sens = fabsf(nsens[0]);
        float a = mdb[0] - sens * 1.0f;           // novelty = 1 (mem empty)
        g_decay[f] = 1.f / (1.f + expf(-a));
    }
}

__global__ void k_matvec(const float* __restrict__ Ws) {
    int m = blockIdx.x;   // f*NB+n in 0..8
    int c = blockIdx.y;   // d-chunk 0..7
    int e = threadIdx.x;  // 0..511
    int f = m / NB;
    __shared__ float xs[64];
    if (e < 64) xs[e] = g_xin[f*D + c*64 + e];
    __syncthreads();
    const float* W = Ws + ((size_t)m*D + c*64)*D + e;
    float acc = 0.f;
    #pragma unroll 8
    for (int dd = 0; dd < 64; dd++) acc = fmaf(xs[dd], W[(size_t)dd*D], acc);
    g_part[(m*8 + c)*D + e] = acc;
}

__global__ void k_foam(int t, const int* __restrict__ tokens, const float* __restrict__ E,
                       const float* __restrict__ mdb, const float* __restrict__ nsens) {
    int f = blockIdx.x, e = threadIdx.x;
    __shared__ float sh[32];
    __shared__ float bcast[8];
    float decay = g_decay[f];

    float s[NB];
    #pragma unroll
    for (int n = 0; n < NB; n++) {
        float a = 0.f;
        #pragma unroll
        for (int c = 0; c < 8; c++) a += g_part[((f*NB+n)*8 + c)*D + e];
        s[n] = a;
    }
    // mean-coupling equilibration: 3 iterations, replicated like reference
    #pragma unroll
    for (int it = 0; it < 3; it++) {
        float m = (s[0] + s[1] + s[2]) * (1.0f/3.0f);
        #pragma unroll
        for (int n = 0; n < NB; n++) s[n] += 0.3f * (m - s[n]);
    }
    float nsq0 = blockReduceSum512(s[0]*s[0], sh);
    float nsq1 = blockReduceSum512(s[1]*s[1], sh);
    float nsq2 = blockReduceSum512(s[2]*s[2], sh);
    if (e == 0) {
        float nr[3] = {sqrtf(nsq0), sqrtf(nsq1), sqrtf(nsq2)};
        float mx = fmaxf(fmaxf(2.f*nr[0], 2.f*nr[1]), 2.f*nr[2]);
        float ex[3], se = 0.f;
        #pragma unroll
        for (int n = 0; n < 3; n++) { ex[n] = expf(2.f*nr[n] - mx); se += ex[n]; }
        #pragma unroll
        for (int n = 0; n < 3; n++) {
            g_w[(t*NF+f)*NB + n] = ex[n] / se;
            bcast[n] = 1.f / (nr[n] + 1e-10f);
        }
    }
    __syncthreads();
    float mem[NB];
    #pragma unroll
    for (int n = 0; n < NB; n++) {
        g_U[((t*NF+f)*NB + n)*D + e] = s[n] * bcast[n];
        float mo = g_memory[(f*NB+n)*D + e];
        mem[n] = decay*mo + (1.f - decay)*s[n];
        g_memory[(f*NB+n)*D + e] = mem[n];
    }
    if (t < T-1) {
        float x = E[(size_t)tokens[t+1]*D + e];
        float mm = (mem[0] + mem[1] + mem[2]) * (1.0f/3.0f);
        float mmsq = blockReduceSum512(mm*mm, sh);
        float dot  = blockReduceSum512(x*mm, sh);
        float xsq  = blockReduceSum512(x*x, sh);
        if (e == 0) {
            float mn = sqrtf(mmsq) + 1e-10f;
            float xn = sqrtf(xsq) + 1e-10f;
            float nov = (mn > 1e-8f) ? (1.f - dot/(xn*mn)) : 1.f;
            float a = mdb[0] - fabsf(nsens[0]) * nov;
            float dn = 1.f / (1.f + expf(-a));
            g_decay[f] = dn;
            bcast[4] = dn;
        }
        __syncthreads();
        g_xin[f*D + e] = x + bcast[4]*mm;
    }
}

// ---------------- phase 2: P = E @ U^T (skinny GEMM, 36 cols) ----------------
__global__ void __launch_bounds__(256) k_P(const float* __restrict__ E) {
    __shared__ float Es[16*513];
    __shared__ float Us[16*37];
    int tid = threadIdx.x;
    int v0 = blockIdx.x * 512;
    int d0 = blockIdx.y * 256;
    float acc0[NJ], acc1[NJ];
    #pragma unroll
    for (int j = 0; j < NJ; j++) { acc0[j] = 0.f; acc1[j] = 0.f; }

    for (int c = 0; c < 16; c++) {
        int db = d0 + c*16;
        __syncthreads();
        #pragma unroll
        for (int it = 0; it < 32; it++) {
            int flat = it*256 + tid;
            int dd = flat & 15, vl = flat >> 4;
            Es[dd*513 + vl] = E[(size_t)(v0+vl)*D + db + dd];
        }
        for (int flat = tid; flat < 16*NJ; flat += 256) {
            int dd = flat / NJ, j = flat - dd*NJ;
            Us[dd*37 + j] = g_U[j*D + db + dd];
        }
        __syncthreads();
        #pragma unroll
        for (int dd = 0; dd < 16; dd++) {
            float ev0 = Es[dd*513 + tid];
            float ev1 = Es[dd*513 + tid + 256];
            #pragma unroll
            for (int j = 0; j < NJ; j++) {
                float u = Us[dd*37 + j];
                acc0[j] = fmaf(ev0, u, acc0[j]);
                acc1[j] = fmaf(ev1, u, acc1[j]);
            }
        }
    }
    float* P = g_P + (size_t)blockIdx.y * NJ * VOCAB;
    #pragma unroll
    for (int j = 0; j < NJ; j++) {
        P[(size_t)j*VOCAB + v0 + tid]       = acc0[j];
        P[(size_t)j*VOCAB + v0 + tid + 256] = acc1[j];
    }
}

// ---------------- per-foam dists (unnormalized) + partial reductions ----------------
__global__ void k_dists(float* __restrict__ out_d) {
    int t = blockIdx.y;
    int v = blockIdx.x * 512 + threadIdx.x;
    int lane = threadIdx.x & 31, wid = threadIdx.x >> 5;
    __shared__ float wsh[9];
    __shared__ float wred[16*12];
    if (threadIdx.x < 9) wsh[threadIdx.x] = g_w[t*9 + threadIdx.x];
    __syncthreads();
    float p[9];
    #pragma unroll
    for (int j = 0; j < 9; j++) {
        int col = t*9 + j;
        p[j] = g_P[(size_t)col*VOCAB + v] + g_P[(size_t)(NJ+col)*VOCAB + v];
    }
    float ef[3], zf[3];
    #pragma unroll
    for (int f = 0; f < 3; f++) {
        float z = wsh[f*3+0]*p[f*3+0]*p[f*3+0]
                + wsh[f*3+1]*p[f*3+1]*p[f*3+1]
                + wsh[f*3+2]*p[f*3+2]*p[f*3+2];
        zf[f] = z; ef[f] = expf(z);
        out_d[((size_t)(t*3+f))*VOCAB + v] = ef[f];
    }
    float vals[12] = { ef[0], ef[1], ef[2],
                       ef[0]*zf[0], ef[1]*zf[1], ef[2]*zf[2],
                       ef[0]*ef[0], ef[0]*ef[1], ef[0]*ef[2],
                       ef[1]*ef[1], ef[1]*ef[2], ef[2]*ef[2] };
    #pragma unroll
    for (int k = 0; k < 12; k++) {
        #pragma unroll
        for (int o = 16; o > 0; o >>= 1) vals[k] += __shfl_down_sync(0xffffffffu, vals[k], o);
    }
    if (lane == 0) {
        #pragma unroll
        for (int k = 0; k < 12; k++) wred[wid*12 + k] = vals[k];
    }
    __syncthreads();
    if (threadIdx.x < 12) {
        float s = 0.f;
        #pragma unroll
        for (int w = 0; w < 16; w++) s += wred[w*12 + threadIdx.x];
        g_red5[(t*64 + blockIdx.x)*12 + threadIdx.x] = s;
    }
}

// ---------------- meta weights + 9x9 eigen ----------------
__global__ void k_meta(float* __restrict__ out_w, float* __restrict__ out_S,
                       const float* __restrict__ mt) {
    int t = blockIdx.x;
    int tid = threadIdx.x;
    __shared__ float red[12];
    __shared__ float gram[45];
    if (tid < 12) {
        float s = 0.f;
        for (int b = 0; b < 64; b++) s += g_red5[(t*64 + b)*12 + tid];
        red[tid] = s;
    }
    // Gram of 9 normalized vectors (45 unique pairs), warp per pair
    int w = tid >> 5, lane = tid & 31;
    for (int pr = w; pr < 45; pr += 16) {
        int i = 0, rem = pr;
        while (rem > i) { rem -= (i + 1); i++; }
        int j = rem; // pair (i,j), j<=i, idx = i(i+1)/2+j
        float s = 0.f;
        const float* ui = g_U + (size_t)(t*9 + i)*D;
        const float* uj = g_U + (size_t)(t*9 + j)*D;
        for (int e = lane; e < D; e += 32) s += ui[e]*uj[e];
        #pragma unroll
        for (int o = 16; o > 0; o >>= 1) s += __shfl_down_sync(0xffffffffu, s, o);
        if (lane == 0) gram[pr] = s;
    }
    __syncthreads();
    if (tid == 0) {
        const float MAXENT = logf(32768.0f);
        float S[3]  = { red[0], red[1], red[2] };
        float Tm[3] = { red[3], red[4], red[5] };
        float G00 = red[6], G01 = red[7], G02 = red[8];
        float G11 = red[9], G12 = red[10], G22 = red[11];
        float H[3], conc[3], np[3];
        #pragma unroll
        for (int f = 0; f < 3; f++) {
            H[f] = logf(S[f]) - Tm[f]/S[f];
            conc[f] = 1.f - H[f]/MAXENT;
        }
        np[0] = sqrtf(G00)/S[0] + 1e-10f;
        np[1] = sqrtf(G11)/S[1] + 1e-10f;
        np[2] = sqrtf(G22)/S[2] + 1e-10f;
        float A01 = (G01/(S[0]*S[1]))/(np[0]*np[1]);
        float A02 = (G02/(S[0]*S[2]))/(np[0]*np[2]);
        float A12 = (G12/(S[1]*S[2]))/(np[1]*np[2]);
        float agree[3] = { 0.5f*(A01+A02), 0.5f*(A01+A12), 0.5f*(A02+A12) };
        float temp = fmaxf(fabsf(mt[0]), 0.01f);
        float l[3], mx = -1e30f;
        #pragma unroll
        for (int f = 0; f < 3; f++) { l[f] = conc[f]*agree[f]/temp; mx = fmaxf(mx, l[f]); }
        float ex[3], se = 0.f;
        #pragma unroll
        for (int f = 0; f < 3; f++) { ex[f] = expf(l[f]-mx); se += ex[f]; }
        float c9[9];
        #pragma unroll
        for (int f = 0; f < 3; f++) {
            float wt = ex[f]/se;
            out_w[t*3 + f] = wt;
            g_invSf[t*3 + f] = 1.f/S[f];
            #pragma unroll
            for (int n = 0; n < 3; n++) {
                c9[f*3+n] = wt * g_w[(t*3+f)*3 + n];
                g_c[t*9 + f*3 + n] = c9[f*3+n];
            }
        }
        // M = C^{1/2} G C^{1/2}, 9x9 Jacobi eigenvalues
        float A[9][9];
        for (int i = 0; i < 9; i++)
            for (int j = 0; j < 9; j++) {
                int a = i > j ? i : j, b = i > j ? j : i;
                A[i][j] = sqrtf(c9[i]*c9[j]) * gram[a*(a+1)/2 + b];
            }
        for (int sweep = 0; sweep < 20; sweep++) {
            for (int p = 0; p < 8; p++)
                for (int q = p+1; q < 9; q++) {
                    float apq = A[p][q];
                    if (fabsf(apq) < 1e-18f) continue;
                    float theta = (A[q][q] - A[p][p]) / (2.f*apq);
                    float tt = (theta >= 0.f ? 1.f : -1.f) /
                               (fabsf(theta) + sqrtf(theta*theta + 1.f));
                    float cc = rsqrtf(tt*tt + 1.f);
                    float ss = tt*cc;
                    for (int k = 0; k < 9; k++) {
                        float akp = A[k][p], akq = A[k][q];
                        A[k][p] = cc*akp - ss*akq;
                        A[k][q] = ss*akp + cc*akq;
                    }
                    for (int k = 0; k < 9; k++) {
                        float apk = A[p][k], aqk = A[q][k];
                        A[p][k] = cc*apk - ss*aqk;
                        A[q][k] = ss*apk + cc*aqk;
                    }
                }
        }
        float lam[9], sum = 503.0f * 1e-12f;
        for (int i = 0; i < 9; i++) { lam[i] = fmaxf(A[i][i], 1e-12f); sum += lam[i]; }
        float inv = 1.f/sum, Sr = 0.f;
        for (int i = 0; i < 9; i++) {
            float pp = lam[i]*inv;
            Sr -= pp * fmaxf(logf(pp), -100.f);
        }
        float pz = 1e-12f*inv;
        Sr -= 503.f * pz * fmaxf(logf(pz), -100.f);
        out_S[t] = Sr;
        g_Srho[t] = Sr;
    }
}

// ---------------- token logits + dist normalize ----------------
__global__ void k_token(float* __restrict__ out_tok, float* __restrict__ out_d) {
    int t = blockIdx.y;
    int v = blockIdx.x * 512 + threadIdx.x;
    int lane = threadIdx.x & 31, wid = threadIdx.x >> 5;
    __shared__ float csh[9];
    __shared__ float isf[3];
    __shared__ float wred[16*2];
    if (threadIdx.x < 9) csh[threadIdx.x] = g_c[t*9 + threadIdx.x];
    if (threadIdx.x < 3) isf[threadIdx.x] = g_invSf[t*3 + threadIdx.x];
    __syncthreads();
    float z = 0.f;
    #pragma unroll
    for (int j = 0; j < 9; j++) {
        int col = t*9 + j;
        float p = g_P[(size_t)col*VOCAB + v] + g_P[(size_t)(NJ+col)*VOCAB + v];
        z = fmaf(csh[j]*p, p, z);
    }
    float e = expf(z);
    out_tok[(size_t)t*VOCAB + v] = e;
    #pragma unroll
    for (int f = 0; f < 3; f++) {
        size_t idx = ((size_t)(t*3+f))*VOCAB + v;
        out_d[idx] = out_d[idx] * isf[f];
    }
    float v0 = e, v1 = e*z;
    #pragma unroll
    for (int o = 16; o > 0; o >>= 1) {
        v0 += __shfl_down_sync(0xffffffffu, v0, o);
        v1 += __shfl_down_sync(0xffffffffu, v1, o);
    }
    if (lane == 0) { wred[wid*2] = v0; wred[wid*2+1] = v1; }
    __syncthreads();
    if (threadIdx.x < 2) {
        float s = 0.f;
        #pragma unroll
        for (int w2 = 0; w2 < 16; w2++) s += wred[w2*2 + threadIdx.x];
        g_red7[(t*64 + blockIdx.x)*2 + threadIdx.x] = s;
    }
}

__global__ void k_scal(float* __restrict__ out_H, float* __restrict__ out_F) {
    int t = blockIdx.x;
    __shared__ float sh[2];
    if (threadIdx.x < 2) {
        float s = 0.f;
        for (int b = 0; b < 64; b++) s += g_red7[(t*64 + b)*2 + threadIdx.x];
        sh[threadIdx.x] = s;
    }
    __syncthreads();
    if (threadIdx.x == 0) {
        float S = sh[0], Tm = sh[1];
        float H = logf(S) - Tm/S;
        out_H[t] = H;
        out_F[t] = H - g_Srho[t];
        g_invStok[t] = 1.f/S;
    }
}

__global__ void k_scale_tok(float* __restrict__ out_tok) {
    int t = blockIdx.y;
    int v = blockIdx.x * 512 + threadIdx.x;
    out_tok[(size_t)t*VOCAB + v] *= g_invStok[t];
}

// ---------------- rho_meta materialization (rank-9) ----------------
__global__ void k_rho(float* __restrict__ out_rho) {
    int t = blockIdx.y;
    int tid = threadIdx.x;
    __shared__ float Us[9][512];
    __shared__ float cs[9];
    #pragma unroll
    for (int k = 0; k < 9; k++) Us[k][tid] = g_U[(size_t)(t*9 + k)*D + tid];
    if (tid < 9) cs[tid] = g_c[t*9 + tid];
    __syncthreads();
    int i0 = blockIdx.x * 8;
    #pragma unroll
    for (int ii = 0; ii < 8; ii++) {
        int i = i0 + ii;
        float a = 0.f;
        #pragma unroll
        for (int k = 0; k < 9; k++) a = fmaf(cs[k]*Us[k][i], Us[k][tid], a);
        out_rho[((size_t)t*D + i)*D + tid] = a;
    }
}

// ---------------- launch ----------------
extern "C" void kernel_launch(void* const* d_in, const int* in_sizes, int n_in,
                              void* d_out, int out_size) {
    (void)in_sizes; (void)n_in; (void)out_size;
    const int*   tokens = (const int*)d_in[0];
    const float* E      = (const float*)d_in[1];
    const float* Ws     = (const float*)d_in[2];
    const float* mt     = (const float*)d_in[3];
    const float* mdb    = (const float*)d_in[4];
    const float* ns     = (const float*)d_in[5];

    float* out     = (float*)d_out;
    float* out_tok = out;                         // [4, 32768]
    float* out_rho = out_tok + T*VOCAB;           // [4, 512, 512]
    float* out_w   = out_rho + (size_t)T*D*D;     // [4, 3]
    float* out_S   = out_w + T*NF;                // [4]
    float* out_H   = out_S + T;                   // [4]
    float* out_F   = out_H + T;                   // [4]
    float* out_d   = out_F + T;                   // [4, 3, 32768]

    k_init<<<NF, D>>>(tokens, E, mdb, ns);
    for (int t = 0; t < T; t++) {
        k_matvec<<<dim3(NF*NB, 8), D>>>(Ws);
        k_foam<<<NF, D>>>(t, tokens, E, mdb, ns);
    }
    k_P<<<dim3(64, 2), 256>>>(E);
    k_dists<<<dim3(64, T), 512>>>(out_d);
    k_meta<<<T, 512>>>(out_w, out_S, mt);
    k_token<<<dim3(64, T), 512>>>(out_tok, out_d);
    k_scal<<<T, 32>>>(out_H, out_F);
    k_scale_tok<<<dim3(64, T), 512>>>(out_tok);
    k_rho<<<dim3(64, T), 512>>>(out_rho);
}

// round 2
// speedup vs baseline: 1.0695x; 1.0695x over previous
#include <cuda_runtime.h>
#include <math.h>

#define VOCAB 32768
#define D 512
#define NB 3
#define NF 3
#define T 4
#define NJ 36   // T*NF*NB

// ---------------- scratch (device globals; no allocation) ----------------
__device__ float g_memory[NF*NB*D];
__device__ float g_xin[NF*D];
__device__ float g_decay[NF];
__device__ float g_part[NF*NB*32*D];
__device__ float g_U[NJ*D];          // [t][f][n][d], j = t*9+f*3+n
__device__ float g_w[NJ];            // bubble weights [t][f][n]
__device__ float g_Z[T*NF*VOCAB];    // zf = born(rho_f) logits
__device__ float g_red5[T*128*12];
__device__ float g_c[NJ];            // meta coeffs c = weights_f * w_fn
__device__ float g_wt[T*NF];         // meta foam weights
__device__ float g_invSf[T*NF];
__device__ float g_Srho[T];
__device__ float g_red7[T*64*2];
__device__ float g_invStok[T];

// ---------------- helpers ----------------
__device__ __forceinline__ float blockReduceSum512(float v, float* sh) {
    #pragma unroll
    for (int o = 16; o > 0; o >>= 1) v += __shfl_down_sync(0xffffffffu, v, o);
    int lane = threadIdx.x & 31, wid = threadIdx.x >> 5;
    if (lane == 0) sh[wid] = v;
    __syncthreads();
    float r;
    if (wid == 0) {
        r = (lane < 16) ? sh[lane] : 0.f;
        #pragma unroll
        for (int o = 8; o > 0; o >>= 1) r += __shfl_down_sync(0xffffffffu, r, o);
        if (lane == 0) sh[0] = r;
    }
    __syncthreads();
    r = sh[0];
    __syncthreads();
    return r;
}

__device__ __forceinline__ void fma2(unsigned long long& d,
                                     unsigned long long a, unsigned long long b) {
    asm("fma.rn.f32x2 %0, %1, %2, %0;" : "+l"(d) : "l"(a), "l"(b));
}
__device__ __forceinline__ void unpack2(float& lo, float& hi, unsigned long long v) {
    asm("mov.b64 {%0, %1}, %2;" : "=f"(lo), "=f"(hi) : "l"(v));
}

// ---------------- phase 1: foam recurrence ----------------
__global__ void k_matvec(int t, const int* __restrict__ tokens,
                         const float* __restrict__ E, const float* __restrict__ Ws) {
    int m = blockIdx.x;   // f*NB+n in 0..8
    int c = blockIdx.y;   // d-chunk 0..31 (16 each)
    int e = threadIdx.x;  // 0..511
    int f = m / NB;
    __shared__ float xs[16];
    if (e < 16) {
        int d = c*16 + e;
        xs[e] = (t == 0) ? E[(size_t)tokens[0]*D + d] : g_xin[f*D + d];
    }
    __syncthreads();
    const float* W = Ws + ((size_t)m*D + c*16)*D + e;
    float acc = 0.f;
    #pragma unroll
    for (int dd = 0; dd < 16; dd++) acc = fmaf(xs[dd], W[(size_t)dd*D], acc);
    g_part[(m*32 + c)*D + e] = acc;
}

__global__ void k_foam(int t, const int* __restrict__ tokens, const float* __restrict__ E,
                       const float* __restrict__ mdb, const float* __restrict__ nsens) {
    int f = blockIdx.x, e = threadIdx.x;
    __shared__ float sh[32];
    __shared__ float bcast[8];
    float decay;
    if (t == 0) {
        float a = mdb[0] - fabsf(nsens[0]);  // novelty = 1 (memory empty)
        decay = 1.f / (1.f + expf(-a));
    } else {
        decay = g_decay[f];
    }

    float s[NB];
    #pragma unroll
    for (int n = 0; n < NB; n++) {
        float a = 0.f;
        #pragma unroll
        for (int c = 0; c < 32; c++) a += g_part[((f*NB+n)*32 + c)*D + e];
        s[n] = a;
    }
    // mean-coupling equilibration: 3 iterations
    #pragma unroll
    for (int it = 0; it < 3; it++) {
        float m = (s[0] + s[1] + s[2]) * (1.0f/3.0f);
        #pragma unroll
        for (int n = 0; n < NB; n++) s[n] += 0.3f * (m - s[n]);
    }
    float nsq0 = blockReduceSum512(s[0]*s[0], sh);
    float nsq1 = blockReduceSum512(s[1]*s[1], sh);
    float nsq2 = blockReduceSum512(s[2]*s[2], sh);
    if (e == 0) {
        float nr[3] = {sqrtf(nsq0), sqrtf(nsq1), sqrtf(nsq2)};
        float mx = fmaxf(fmaxf(2.f*nr[0], 2.f*nr[1]), 2.f*nr[2]);
        float ex[3], se = 0.f;
        #pragma unroll
        for (int n = 0; n < 3; n++) { ex[n] = expf(2.f*nr[n] - mx); se += ex[n]; }
        #pragma unroll
        for (int n = 0; n < 3; n++) {
            g_w[(t*NF+f)*NB + n] = ex[n] / se;
            bcast[n] = 1.f / (nr[n] + 1e-10f);
        }
    }
    __syncthreads();
    float mem[NB];
    #pragma unroll
    for (int n = 0; n < NB; n++) {
        g_U[((t*NF+f)*NB + n)*D + e] = s[n] * bcast[n];
        float mo = (t == 0) ? 0.f : g_memory[(f*NB+n)*D + e];
        mem[n] = decay*mo + (1.f - decay)*s[n];
        g_memory[(f*NB+n)*D + e] = mem[n];
    }
    if (t < T-1) {
        float x = E[(size_t)tokens[t+1]*D + e];
        float mm = (mem[0] + mem[1] + mem[2]) * (1.0f/3.0f);
        float mmsq = blockReduceSum512(mm*mm, sh);
        float dot  = blockReduceSum512(x*mm, sh);
        float xsq  = blockReduceSum512(x*x, sh);
        if (e == 0) {
            float mn = sqrtf(mmsq) + 1e-10f;
            float xn = sqrtf(xsq) + 1e-10f;
            float nov = (mn > 1e-8f) ? (1.f - dot/(xn*mn)) : 1.f;
            float a = mdb[0] - fabsf(nsens[0]) * nov;
            float dn = 1.f / (1.f + expf(-a));
            g_decay[f] = dn;
            bcast[4] = dn;
        }
        __syncthreads();
        g_xin[f*D + e] = x + bcast[4]*mm;
    }
}

// ---------------- phase 2: fused P = E@U^T + born logits + dists ----------------
// grid (128, 2): blockIdx.x = v-block (256 v), blockIdx.y = t-pair {0,1},{2,3}
// 128 threads, each handles v-pair (v0+2*tid, v0+2*tid+1) via f32x2 packed FMA.
__global__ void __launch_bounds__(128) k_P(const float* __restrict__ E,
                                           float* __restrict__ out_d) {
    __shared__ float Es[16][258];
    __shared__ float2 Us2[16][18];
    __shared__ float wsh[18];
    __shared__ float wred[4][24];
    int tid = threadIdx.x;
    int v0 = blockIdx.x * 256;
    int y = blockIdx.y;
    int jbase = y * 18;
    if (tid < 18) wsh[tid] = g_w[jbase + tid];

    unsigned long long acc[18];
    #pragma unroll
    for (int j = 0; j < 18; j++) acc[j] = 0ull;

    for (int c = 0; c < 32; c++) {
        int db = c * 16;
        __syncthreads();
        #pragma unroll
        for (int it = 0; it < 32; it++) {
            int flat = it*128 + tid;
            int dd = flat & 15, vl = flat >> 4;
            Es[dd][vl] = E[(size_t)(v0+vl)*D + db + dd];
        }
        #pragma unroll
        for (int flat = tid; flat < 16*18; flat += 128) {
            int dd = flat / 18, jj = flat - dd*18;
            float u = g_U[(size_t)(jbase+jj)*D + db + dd];
            Us2[dd][jj] = make_float2(u, u);
        }
        __syncthreads();
        #pragma unroll
        for (int dd = 0; dd < 16; dd++) {
            unsigned long long ev = *(const unsigned long long*)&Es[dd][tid*2];
            #pragma unroll
            for (int jj = 0; jj < 18; jj++) {
                unsigned long long u2 = *(const unsigned long long*)&Us2[dd][jj];
                fma2(acc[jj], ev, u2);
            }
        }
    }

    // epilogue: per t (2 of them), per foam f: zf = sum_n w_n p_n^2
    int lane = tid & 31, wid = tid >> 5;
    #pragma unroll
    for (int tt = 0; tt < 2; tt++) {
        int t = 2*y + tt;
        float vals[12];
        float ef0[3], ef1[3];
        #pragma unroll
        for (int f = 0; f < 3; f++) {
            float z0 = 0.f, z1 = 0.f;
            #pragma unroll
            for (int n = 0; n < 3; n++) {
                int jj = tt*9 + f*3 + n;
                float p0, p1;
                unpack2(p0, p1, acc[jj]);
                float w = wsh[jj];
                z0 = fmaf(w*p0, p0, z0);
                z1 = fmaf(w*p1, p1, z1);
            }
            float e0 = expf(z0), e1 = expf(z1);
            ef0[f] = e0; ef1[f] = e1;
            size_t base = ((size_t)(t*3+f))*VOCAB + v0 + 2*tid;
            *(float2*)&out_d[base] = make_float2(e0, e1);
            *(float2*)&g_Z[base]   = make_float2(z0, z1);
            vals[f]   = e0 + e1;
            vals[3+f] = e0*z0 + e1*z1;
        }
        vals[6]  = ef0[0]*ef0[0] + ef1[0]*ef1[0];
        vals[7]  = ef0[0]*ef0[1] + ef1[0]*ef1[1];
        vals[8]  = ef0[0]*ef0[2] + ef1[0]*ef1[2];
        vals[9]  = ef0[1]*ef0[1] + ef1[1]*ef1[1];
        vals[10] = ef0[1]*ef0[2] + ef1[1]*ef1[2];
        vals[11] = ef0[2]*ef0[2] + ef1[2]*ef1[2];
        #pragma unroll
        for (int k = 0; k < 12; k++) {
            #pragma unroll
            for (int o = 16; o > 0; o >>= 1)
                vals[k] += __shfl_down_sync(0xffffffffu, vals[k], o);
        }
        if (lane == 0) {
            #pragma unroll
            for (int k = 0; k < 12; k++) wred[wid][tt*12 + k] = vals[k];
        }
    }
    __syncthreads();
    if (tid < 24) {
        int tt = tid / 12, k = tid % 12;
        int t = 2*y + tt;
        float s = wred[0][tid] + wred[1][tid] + wred[2][tid] + wred[3][tid];
        g_red5[(t*128 + blockIdx.x)*12 + k] = s;
    }
}

// ---------------- meta weights + 9x9 eigen ----------------
__global__ void k_meta(float* __restrict__ out_w, float* __restrict__ out_S,
                       const float* __restrict__ mt) {
    int t = blockIdx.x;
    int tid = threadIdx.x;
    __shared__ float red[12];
    __shared__ float gram[45];
    if (tid < 12) {
        float s = 0.f;
        for (int b = 0; b < 128; b++) s += g_red5[(t*128 + b)*12 + tid];
        red[tid] = s;
    }
    int w = tid >> 5, lane = tid & 31;
    for (int pr = w; pr < 45; pr += 16) {
        int i = 0, rem = pr;
        while (rem > i) { rem -= (i + 1); i++; }
        int j = rem;
        float s = 0.f;
        const float* ui = g_U + (size_t)(t*9 + i)*D;
        const float* uj = g_U + (size_t)(t*9 + j)*D;
        for (int e = lane; e < D; e += 32) s += ui[e]*uj[e];
        #pragma unroll
        for (int o = 16; o > 0; o >>= 1) s += __shfl_down_sync(0xffffffffu, s, o);
        if (lane == 0) gram[pr] = s;
    }
    __syncthreads();
    if (tid == 0) {
        const float MAXENT = logf(32768.0f);
        float S[3]  = { red[0], red[1], red[2] };
        float Tm[3] = { red[3], red[4], red[5] };
        float G00 = red[6], G01 = red[7], G02 = red[8];
        float G11 = red[9], G12 = red[10], G22 = red[11];
        float H[3], conc[3], np[3];
        #pragma unroll
        for (int f = 0; f < 3; f++) {
            H[f] = logf(S[f]) - Tm[f]/S[f];
            conc[f] = 1.f - H[f]/MAXENT;
        }
        np[0] = sqrtf(G00)/S[0] + 1e-10f;
        np[1] = sqrtf(G11)/S[1] + 1e-10f;
        np[2] = sqrtf(G22)/S[2] + 1e-10f;
        float A01 = (G01/(S[0]*S[1]))/(np[0]*np[1]);
        float A02 = (G02/(S[0]*S[2]))/(np[0]*np[2]);
        float A12 = (G12/(S[1]*S[2]))/(np[1]*np[2]);
        float agree[3] = { 0.5f*(A01+A02), 0.5f*(A01+A12), 0.5f*(A02+A12) };
        float temp = fmaxf(fabsf(mt[0]), 0.01f);
        float l[3], mx = -1e30f;
        #pragma unroll
        for (int f = 0; f < 3; f++) { l[f] = conc[f]*agree[f]/temp; mx = fmaxf(mx, l[f]); }
        float ex[3], se = 0.f;
        #pragma unroll
        for (int f = 0; f < 3; f++) { ex[f] = expf(l[f]-mx); se += ex[f]; }
        float c9[9];
        #pragma unroll
        for (int f = 0; f < 3; f++) {
            float wt = ex[f]/se;
            out_w[t*3 + f] = wt;
            g_wt[t*3 + f] = wt;
            g_invSf[t*3 + f] = 1.f/S[f];
            #pragma unroll
            for (int n = 0; n < 3; n++) {
                c9[f*3+n] = wt * g_w[(t*3+f)*3 + n];
                g_c[t*9 + f*3 + n] = c9[f*3+n];
            }
        }
        float A[9][9];
        for (int i = 0; i < 9; i++)
            for (int j = 0; j < 9; j++) {
                int a = i > j ? i : j, b = i > j ? j : i;
                A[i][j] = sqrtf(c9[i]*c9[j]) * gram[a*(a+1)/2 + b];
            }
        for (int sweep = 0; sweep < 20; sweep++) {
            for (int p = 0; p < 8; p++)
                for (int q = p+1; q < 9; q++) {
                    float apq = A[p][q];
                    if (fabsf(apq) < 1e-18f) continue;
                    float theta = (A[q][q] - A[p][p]) / (2.f*apq);
                    float tt = (theta >= 0.f ? 1.f : -1.f) /
                               (fabsf(theta) + sqrtf(theta*theta + 1.f));
                    float cc = rsqrtf(tt*tt + 1.f);
                    float ss = tt*cc;
                    for (int k = 0; k < 9; k++) {
                        float akp = A[k][p], akq = A[k][q];
                        A[k][p] = cc*akp - ss*akq;
                        A[k][q] = ss*akp + cc*akq;
                    }
                    for (int k = 0; k < 9; k++) {
                        float apk = A[p][k], aqk = A[q][k];
                        A[p][k] = cc*apk - ss*aqk;
                        A[q][k] = ss*apk + cc*aqk;
                    }
                }
        }
        float lam[9], sum = 503.0f * 1e-12f;
        for (int i = 0; i < 9; i++) { lam[i] = fmaxf(A[i][i], 1e-12f); sum += lam[i]; }
        float inv = 1.f/sum, Sr = 0.f;
        for (int i = 0; i < 9; i++) {
            float pp = lam[i]*inv;
            Sr -= pp * fmaxf(logf(pp), -100.f);
        }
        float pz = 1e-12f*inv;
        Sr -= 503.f * pz * fmaxf(logf(pz), -100.f);
        out_S[t] = Sr;
        g_Srho[t] = Sr;
    }
}

// ---------------- token logits (from zf) + dist normalize ----------------
__global__ void k_token(float* __restrict__ out_tok, float* __restrict__ out_d) {
    int t = blockIdx.y;
    int v = blockIdx.x * 512 + threadIdx.x;
    int lane = threadIdx.x & 31, wid = threadIdx.x >> 5;
    __shared__ float sh6[6];
    __shared__ float wred[16*2];
    if (threadIdx.x < 3) {
        sh6[threadIdx.x]   = g_wt[t*3 + threadIdx.x];
        sh6[3+threadIdx.x] = g_invSf[t*3 + threadIdx.x];
    }
    __syncthreads();
    float z = 0.f;
    #pragma unroll
    for (int f = 0; f < 3; f++) {
        size_t idx = ((size_t)(t*3+f))*VOCAB + v;
        z = fmaf(sh6[f], g_Z[idx], z);
        out_d[idx] = out_d[idx] * sh6[3+f];
    }
    float e = expf(z);
    out_tok[(size_t)t*VOCAB + v] = e;
    float v0 = e, v1 = e*z;
    #pragma unroll
    for (int o = 16; o > 0; o >>= 1) {
        v0 += __shfl_down_sync(0xffffffffu, v0, o);
        v1 += __shfl_down_sync(0xffffffffu, v1, o);
    }
    if (lane == 0) { wred[wid*2] = v0; wred[wid*2+1] = v1; }
    __syncthreads();
    if (threadIdx.x < 2) {
        float s = 0.f;
        #pragma unroll
        for (int w2 = 0; w2 < 16; w2++) s += wred[w2*2 + threadIdx.x];
        g_red7[(t*64 + blockIdx.x)*2 + threadIdx.x] = s;
    }
}

__global__ void k_scal(float* __restrict__ out_H, float* __restrict__ out_F) {
    int t = blockIdx.x;
    __shared__ float sh[2];
    if (threadIdx.x < 2) {
        float s = 0.f;
        for (int b = 0; b < 64; b++) s += g_red7[(t*64 + b)*2 + threadIdx.x];
        sh[threadIdx.x] = s;
    }
    __syncthreads();
    if (threadIdx.x == 0) {
        float S = sh[0], Tm = sh[1];
        float H = logf(S) - Tm/S;
        out_H[t] = H;
        out_F[t] = H - g_Srho[t];
        g_invStok[t] = 1.f/S;
    }
}

// ---------------- rho_meta (rank-9) + token prob scaling ----------------
__global__ void k_rho(float* __restrict__ out_rho, float* __restrict__ out_tok) {
    int t = blockIdx.y;
    int tid = threadIdx.x;
    out_tok[(size_t)t*VOCAB + blockIdx.x*512 + tid] *= g_invStok[t];
    __shared__ float Us[9][512];
    __shared__ float cs[9];
    #pragma unroll
    for (int k = 0; k < 9; k++) Us[k][tid] = g_U[(size_t)(t*9 + k)*D + tid];
    if (tid < 9) cs[tid] = g_c[t*9 + tid];
    __syncthreads();
    int i0 = blockIdx.x * 8;
    #pragma unroll
    for (int ii = 0; ii < 8; ii++) {
        int i = i0 + ii;
        float a = 0.f;
        #pragma unroll
        for (int k = 0; k < 9; k++) a = fmaf(cs[k]*Us[k][i], Us[k][tid], a);
        out_rho[((size_t)t*D + i)*D + tid] = a;
    }
}

// ---------------- launch ----------------
extern "C" void kernel_launch(void* const* d_in, const int* in_sizes, int n_in,
                              void* d_out, int out_size) {
    (void)in_sizes; (void)n_in; (void)out_size;
    const int*   tokens = (const int*)d_in[0];
    const float* E      = (const float*)d_in[1];
    const float* Ws     = (const float*)d_in[2];
    const float* mt     = (const float*)d_in[3];
    const float* mdb    = (const float*)d_in[4];
    const float* ns     = (const float*)d_in[5];

    float* out     = (float*)d_out;
    float* out_tok = out;                         // [4, 32768]
    float* out_rho = out_tok + T*VOCAB;           // [4, 512, 512]
    float* out_w   = out_rho + (size_t)T*D*D;     // [4, 3]
    float* out_S   = out_w + T*NF;                // [4]
    float* out_H   = out_S + T;                   // [4]
    float* out_F   = out_H + T;                   // [4]
    float* out_d   = out_F + T;                   // [4, 3, 32768]

    for (int t = 0; t < T; t++) {
        k_matvec<<<dim3(NF*NB, 32), D>>>(t, tokens, E, Ws);
        k_foam<<<NF, D>>>(t, tokens, E, mdb, ns);
    }
    k_P<<<dim3(128, 2), 128>>>(E, out_d);
    k_meta<<<T, 512>>>(out_w, out_S, mt);
    k_token<<<dim3(64, T), 512>>>(out_tok, out_d);
    k_scal<<<T, 32>>>(out_H, out_F);
    k_rho<<<dim3(64, T), 512>>>(out_rho, out_tok);
}

// round 3
// speedup vs baseline: 1.0909x; 1.0200x over previous
#include <cuda_runtime.h>
#include <math.h>

#define VOCAB 32768
#define D 512
#define NB 3
#define NF 3
#define T 4
#define NJ 36   // T*NF*NB
#define P1_BLOCKS 72

// ---------------- scratch (device globals; no allocation) ----------------
__device__ float g_xin[NF*D];
__device__ float g_part[NF*NB*8*D];
__device__ float g_U[NJ*D];          // [t][f][n][d], j = t*9+f*3+n
__device__ float g_w[NJ];            // bubble weights [t][f][n]
__device__ float g_Z[T*NF*VOCAB];    // zf = born(rho_f) logits
__device__ float g_red5[T*128*12];
__device__ float g_c[NJ];            // meta coeffs c = weights_f * w_fn
__device__ float g_wt[T*NF];         // meta foam weights
__device__ float g_invSf[T*NF];
__device__ float g_Srho[T];
__device__ float g_red7[T*64*2];
__device__ float g_invStok[T];
__device__ unsigned g_bar_count;     // zero-init; self-resetting
__device__ unsigned g_bar_epoch;     // monotonic across replays

// ---------------- helpers ----------------
__device__ __forceinline__ float blockReduceSum512(float v, float* sh) {
    #pragma unroll
    for (int o = 16; o > 0; o >>= 1) v += __shfl_down_sync(0xffffffffu, v, o);
    int lane = threadIdx.x & 31, wid = threadIdx.x >> 5;
    if (lane == 0) sh[wid] = v;
    __syncthreads();
    float r;
    if (wid == 0) {
        r = (lane < 16) ? sh[lane] : 0.f;
        #pragma unroll
        for (int o = 8; o > 0; o >>= 1) r += __shfl_down_sync(0xffffffffu, r, o);
        if (lane == 0) sh[0] = r;
    }
    __syncthreads();
    r = sh[0];
    __syncthreads();
    return r;
}

__device__ __forceinline__ void gridSyncAll() {
    __threadfence();
    __syncthreads();
    if (threadIdx.x == 0) {
        unsigned e0 = *(volatile unsigned*)&g_bar_epoch;
        unsigned my = atomicAdd(&g_bar_count, 1u);
        if (my == P1_BLOCKS - 1u) {
            g_bar_count = 0u;
            __threadfence();
            atomicAdd(&g_bar_epoch, 1u);
        } else {
            while (*(volatile unsigned*)&g_bar_epoch == e0) { __nanosleep(64); }
        }
    }
    __syncthreads();
}

__device__ __forceinline__ void fma2(unsigned long long& d,
                                     unsigned long long a, unsigned long long b) {
    asm("fma.rn.f32x2 %0, %1, %2, %0;" : "+l"(d) : "l"(a), "l"(b));
}
__device__ __forceinline__ void unpack2(float& lo, float& hi, unsigned long long v) {
    asm("mov.b64 {%0, %1}, %2;" : "=f"(lo), "=f"(hi) : "l"(v));
}

// ---------------- phase 1: entire foam recurrence, ONE kernel ----------------
// 72 blocks x 512 threads, all co-resident (<=1 block/SM on 148 SMs).
// block b: matvec role m = b/8 (matrix), c = b%8 (64-row d-chunk).
// blocks 0..2 additionally run the foam finalize for f = b.
__global__ void __launch_bounds__(512) k_phase1(
        const int* __restrict__ tokens, const float* __restrict__ E,
        const float* __restrict__ Ws, const float* __restrict__ mdb,
        const float* __restrict__ nsens) {
    int b = blockIdx.x;
    int m = b >> 3, c = b & 7;
    int e = threadIdx.x;
    __shared__ float xs[64];
    __shared__ float sh[32];
    __shared__ float bcast[8];

    // preload this block's W chunk into registers (reused all 4 steps)
    float w[64];
    const float* Wp = Ws + ((size_t)m*D + c*64)*D + e;
    #pragma unroll
    for (int i = 0; i < 64; i++) w[i] = Wp[(size_t)i*D];

    float mem0 = 0.f, mem1 = 0.f, mem2 = 0.f;
    float decay = 0.f;
    float sens = fabsf(nsens[0]);
    float mdb0 = mdb[0];

    for (int t = 0; t < T; t++) {
        // ---- matvec partial: states[m][e] partial over this d-chunk ----
        if (e < 64) {
            xs[e] = (t == 0) ? E[(size_t)tokens[0]*D + c*64 + e]
                             : g_xin[(m/NB)*D + c*64 + e];
        }
        __syncthreads();
        float acc = 0.f;
        #pragma unroll
        for (int i = 0; i < 64; i++) acc = fmaf(xs[i], w[i], acc);
        g_part[(m*8 + c)*D + e] = acc;
        __syncthreads();            // xs reuse guard before next barrier pass
        gridSyncAll();

        // ---- foam finalize on blocks 0..2 ----
        if (b < NF) {
            int f = b;
            if (t == 0) {
                float a = mdb0 - sens;          // novelty = 1 (memory empty)
                decay = 1.f / (1.f + expf(-a));
            }
            float s0 = 0.f, s1 = 0.f, s2 = 0.f;
            #pragma unroll
            for (int cc = 0; cc < 8; cc++) {
                s0 += g_part[((f*NB + 0)*8 + cc)*D + e];
                s1 += g_part[((f*NB + 1)*8 + cc)*D + e];
                s2 += g_part[((f*NB + 2)*8 + cc)*D + e];
            }
            #pragma unroll
            for (int it = 0; it < 3; it++) {
                float mn = (s0 + s1 + s2) * (1.0f/3.0f);
                s0 += 0.3f * (mn - s0);
                s1 += 0.3f * (mn - s1);
                s2 += 0.3f * (mn - s2);
            }
            float nsq0 = blockReduceSum512(s0*s0, sh);
            float nsq1 = blockReduceSum512(s1*s1, sh);
            float nsq2 = blockReduceSum512(s2*s2, sh);
            if (e == 0) {
                float nr[3] = {sqrtf(nsq0), sqrtf(nsq1), sqrtf(nsq2)};
                float mx = fmaxf(fmaxf(2.f*nr[0], 2.f*nr[1]), 2.f*nr[2]);
                float ex[3], se = 0.f;
                #pragma unroll
                for (int n = 0; n < 3; n++) { ex[n] = expf(2.f*nr[n] - mx); se += ex[n]; }
                #pragma unroll
                for (int n = 0; n < 3; n++) {
                    g_w[(t*NF + f)*NB + n] = ex[n] / se;
                    bcast[n] = 1.f / (nr[n] + 1e-10f);
                }
            }
            __syncthreads();
            g_U[((t*NF + f)*NB + 0)*D + e] = s0 * bcast[0];
            g_U[((t*NF + f)*NB + 1)*D + e] = s1 * bcast[1];
            g_U[((t*NF + f)*NB + 2)*D + e] = s2 * bcast[2];
            mem0 = decay*mem0 + (1.f - decay)*s0;
            mem1 = decay*mem1 + (1.f - decay)*s1;
            mem2 = decay*mem2 + (1.f - decay)*s2;
            if (t < T-1) {
                float x = E[(size_t)tokens[t+1]*D + e];
                float mm = (mem0 + mem1 + mem2) * (1.0f/3.0f);
                float mmsq = blockReduceSum512(mm*mm, sh);
                float dot  = blockReduceSum512(x*mm, sh);
                float xsq  = blockReduceSum512(x*x, sh);
                if (e == 0) {
                    float mn = sqrtf(mmsq) + 1e-10f;
                    float xn = sqrtf(xsq) + 1e-10f;
                    float nov = (mn > 1e-8f) ? (1.f - dot/(xn*mn)) : 1.f;
                    float a = mdb0 - sens * nov;
                    bcast[4] = 1.f / (1.f + expf(-a));
                }
                __syncthreads();
                decay = bcast[4];
                g_xin[f*D + e] = x + decay*mm;
            }
        }
        gridSyncAll();
    }
}

// ---------------- phase 2: fused P = E@U^T + born logits z + partials ----------------
// grid (128, 2): blockIdx.x = v-block (256 v), blockIdx.y = t-pair {0,1},{2,3}
// 128 threads, v-pair per thread via f32x2 packed FMA.
__global__ void __launch_bounds__(128) k_P(const float* __restrict__ E) {
    __shared__ float Es[16][258];
    __shared__ float2 Us2[16][18];
    __shared__ float wsh[18];
    __shared__ float wred[4][24];
    int tid = threadIdx.x;
    int v0 = blockIdx.x * 256;
    int y = blockIdx.y;
    int jbase = y * 18;
    if (tid < 18) wsh[tid] = g_w[jbase + tid];

    unsigned long long acc[18];
    #pragma unroll
    for (int j = 0; j < 18; j++) acc[j] = 0ull;

    for (int c = 0; c < 32; c++) {
        int db = c * 16;
        __syncthreads();
        #pragma unroll
        for (int it = 0; it < 32; it++) {
            int flat = it*128 + tid;
            int dd = flat & 15, vl = flat >> 4;
            Es[dd][vl] = E[(size_t)(v0+vl)*D + db + dd];
        }
        #pragma unroll
        for (int flat = tid; flat < 16*18; flat += 128) {
            int dd = flat / 18, jj = flat - dd*18;
            float u = g_U[(size_t)(jbase+jj)*D + db + dd];
            Us2[dd][jj] = make_float2(u, u);
        }
        __syncthreads();
        #pragma unroll
        for (int dd = 0; dd < 16; dd++) {
            unsigned long long ev = *(const unsigned long long*)&Es[dd][tid*2];
            #pragma unroll
            for (int jj = 0; jj < 18; jj++) {
                unsigned long long u2 = *(const unsigned long long*)&Us2[dd][jj];
                fma2(acc[jj], ev, u2);
            }
        }
    }

    int lane = tid & 31, wid = tid >> 5;
    #pragma unroll
    for (int tt = 0; tt < 2; tt++) {
        int t = 2*y + tt;
        float vals[12];
        float ef0[3], ef1[3];
        #pragma unroll
        for (int f = 0; f < 3; f++) {
            float z0 = 0.f, z1 = 0.f;
            #pragma unroll
            for (int n = 0; n < 3; n++) {
                int jj = tt*9 + f*3 + n;
                float p0, p1;
                unpack2(p0, p1, acc[jj]);
                float w = wsh[jj];
                z0 = fmaf(w*p0, p0, z0);
                z1 = fmaf(w*p1, p1, z1);
            }
            float e0 = expf(z0), e1 = expf(z1);
            ef0[f] = e0; ef1[f] = e1;
            size_t base = ((size_t)(t*3+f))*VOCAB + v0 + 2*tid;
            *(float2*)&g_Z[base] = make_float2(z0, z1);
            vals[f]   = e0 + e1;
            vals[3+f] = e0*z0 + e1*z1;
        }
        vals[6]  = ef0[0]*ef0[0] + ef1[0]*ef1[0];
        vals[7]  = ef0[0]*ef0[1] + ef1[0]*ef1[1];
        vals[8]  = ef0[0]*ef0[2] + ef1[0]*ef1[2];
        vals[9]  = ef0[1]*ef0[1] + ef1[1]*ef1[1];
        vals[10] = ef0[1]*ef0[2] + ef1[1]*ef1[2];
        vals[11] = ef0[2]*ef0[2] + ef1[2]*ef1[2];
        #pragma unroll
        for (int k = 0; k < 12; k++) {
            #pragma unroll
            for (int o = 16; o > 0; o >>= 1)
                vals[k] += __shfl_down_sync(0xffffffffu, vals[k], o);
        }
        if (lane == 0) {
            #pragma unroll
            for (int k = 0; k < 12; k++) wred[wid][tt*12 + k] = vals[k];
        }
    }
    __syncthreads();
    if (tid < 24) {
        int tt = tid / 12, k = tid % 12;
        int t = 2*y + tt;
        float s = wred[0][tid] + wred[1][tid] + wred[2][tid] + wred[3][tid];
        g_red5[(t*128 + blockIdx.x)*12 + k] = s;
    }
}

// ---------------- meta weights + 9x9 eigen ----------------
__global__ void k_meta(float* __restrict__ out_w, float* __restrict__ out_S,
                       const float* __restrict__ mt) {
    int t = blockIdx.x;
    int tid = threadIdx.x;
    __shared__ float red[12];
    __shared__ float gram[45];
    if (tid < 12) {
        float s = 0.f;
        for (int b = 0; b < 128; b++) s += g_red5[(t*128 + b)*12 + tid];
        red[tid] = s;
    }
    int w = tid >> 5, lane = tid & 31;
    for (int pr = w; pr < 45; pr += 16) {
        int i = 0, rem = pr;
        while (rem > i) { rem -= (i + 1); i++; }
        int j = rem;
        float s = 0.f;
        const float* ui = g_U + (size_t)(t*9 + i)*D;
        const float* uj = g_U + (size_t)(t*9 + j)*D;
        for (int e = lane; e < D; e += 32) s += ui[e]*uj[e];
        #pragma unroll
        for (int o = 16; o > 0; o >>= 1) s += __shfl_down_sync(0xffffffffu, s, o);
        if (lane == 0) gram[pr] = s;
    }
    __syncthreads();
    if (tid == 0) {
        const float MAXENT = logf(32768.0f);
        float S[3]  = { red[0], red[1], red[2] };
        float Tm[3] = { red[3], red[4], red[5] };
        float G00 = red[6], G01 = red[7], G02 = red[8];
        float G11 = red[9], G12 = red[10], G22 = red[11];
        float H[3], conc[3], np[3];
        #pragma unroll
        for (int f = 0; f < 3; f++) {
            H[f] = logf(S[f]) - Tm[f]/S[f];
            conc[f] = 1.f - H[f]/MAXENT;
        }
        np[0] = sqrtf(G00)/S[0] + 1e-10f;
        np[1] = sqrtf(G11)/S[1] + 1e-10f;
        np[2] = sqrtf(G22)/S[2] + 1e-10f;
        float A01 = (G01/(S[0]*S[1]))/(np[0]*np[1]);
        float A02 = (G02/(S[0]*S[2]))/(np[0]*np[2]);
        float A12 = (G12/(S[1]*S[2]))/(np[1]*np[2]);
        float agree[3] = { 0.5f*(A01+A02), 0.5f*(A01+A12), 0.5f*(A02+A12) };
        float temp = fmaxf(fabsf(mt[0]), 0.01f);
        float l[3], mx = -1e30f;
        #pragma unroll
        for (int f = 0; f < 3; f++) { l[f] = conc[f]*agree[f]/temp; mx = fmaxf(mx, l[f]); }
        float ex[3], se = 0.f;
        #pragma unroll
        for (int f = 0; f < 3; f++) { ex[f] = expf(l[f]-mx); se += ex[f]; }
        float c9[9];
        #pragma unroll
        for (int f = 0; f < 3; f++) {
            float wt = ex[f]/se;
            out_w[t*3 + f] = wt;
            g_wt[t*3 + f] = wt;
            g_invSf[t*3 + f] = 1.f/S[f];
            #pragma unroll
            for (int n = 0; n < 3; n++) {
                c9[f*3+n] = wt * g_w[(t*3+f)*3 + n];
                g_c[t*9 + f*3 + n] = c9[f*3+n];
            }
        }
        float A[9][9];
        for (int i = 0; i < 9; i++)
            for (int j = 0; j < 9; j++) {
                int a = i > j ? i : j, bb = i > j ? j : i;
                A[i][j] = sqrtf(c9[i]*c9[j]) * gram[a*(a+1)/2 + bb];
            }
        for (int sweep = 0; sweep < 20; sweep++) {
            for (int p = 0; p < 8; p++)
                for (int q = p+1; q < 9; q++) {
                    float apq = A[p][q];
                    if (fabsf(apq) < 1e-18f) continue;
                    float theta = (A[q][q] - A[p][p]) / (2.f*apq);
                    float tt = (theta >= 0.f ? 1.f : -1.f) /
                               (fabsf(theta) + sqrtf(theta*theta + 1.f));
                    float cc = rsqrtf(tt*tt + 1.f);
                    float ss = tt*cc;
                    for (int k = 0; k < 9; k++) {
                        float akp = A[k][p], akq = A[k][q];
                        A[k][p] = cc*akp - ss*akq;
                        A[k][q] = ss*akp + cc*akq;
                    }
                    for (int k = 0; k < 9; k++) {
                        float apk = A[p][k], aqk = A[q][k];
                        A[p][k] = cc*apk - ss*aqk;
                        A[q][k] = ss*apk + cc*aqk;
                    }
                }
        }
        float lam[9], sum = 503.0f * 1e-12f;
        for (int i = 0; i < 9; i++) { lam[i] = fmaxf(A[i][i], 1e-12f); sum += lam[i]; }
        float inv = 1.f/sum, Sr = 0.f;
        for (int i = 0; i < 9; i++) {
            float pp = lam[i]*inv;
            Sr -= pp * fmaxf(logf(pp), -100.f);
        }
        float pz = 1e-12f*inv;
        Sr -= 503.f * pz * fmaxf(logf(pz), -100.f);
        out_S[t] = Sr;
        g_Srho[t] = Sr;
    }
}

// ---------------- token logits (from zf) + per-foam dist writes ----------------
__global__ void k_token(float* __restrict__ out_tok, float* __restrict__ out_d) {
    int t = blockIdx.y;
    int v = blockIdx.x * 512 + threadIdx.x;
    int lane = threadIdx.x & 31, wid = threadIdx.x >> 5;
    __shared__ float sh6[6];
    __shared__ float wred[16*2];
    if (threadIdx.x < 3) {
        sh6[threadIdx.x]   = g_wt[t*3 + threadIdx.x];
        sh6[3+threadIdx.x] = g_invSf[t*3 + threadIdx.x];
    }
    __syncthreads();
    float z = 0.f;
    #pragma unroll
    for (int f = 0; f < 3; f++) {
        size_t idx = ((size_t)(t*3+f))*VOCAB + v;
        float zf = g_Z[idx];
        z = fmaf(sh6[f], zf, z);
        out_d[idx] = expf(zf) * sh6[3+f];
    }
    float e = expf(z);
    out_tok[(size_t)t*VOCAB + v] = e;
    float v0 = e, v1 = e*z;
    #pragma unroll
    for (int o = 16; o > 0; o >>= 1) {
        v0 += __shfl_down_sync(0xffffffffu, v0, o);
        v1 += __shfl_down_sync(0xffffffffu, v1, o);
    }
    if (lane == 0) { wred[wid*2] = v0; wred[wid*2+1] = v1; }
    __syncthreads();
    if (threadIdx.x < 2) {
        float s = 0.f;
        #pragma unroll
        for (int w2 = 0; w2 < 16; w2++) s += wred[w2*2 + threadIdx.x];
        g_red7[(t*64 + blockIdx.x)*2 + threadIdx.x] = s;
    }
}

__global__ void k_scal(float* __restrict__ out_H, float* __restrict__ out_F) {
    int t = blockIdx.x;
    __shared__ float sh[2];
    if (threadIdx.x < 2) {
        float s = 0.f;
        for (int b = 0; b < 64; b++) s += g_red7[(t*64 + b)*2 + threadIdx.x];
        sh[threadIdx.x] = s;
    }
    __syncthreads();
    if (threadIdx.x == 0) {
        float S = sh[0], Tm = sh[1];
        float H = logf(S) - Tm/S;
        out_H[t] = H;
        out_F[t] = H - g_Srho[t];
        g_invStok[t] = 1.f/S;
    }
}

// ---------------- rho_meta (rank-9) + token prob scaling ----------------
__global__ void k_rho(float* __restrict__ out_rho, float* __restrict__ out_tok) {
    int t = blockIdx.y;
    int tid = threadIdx.x;
    out_tok[(size_t)t*VOCAB + blockIdx.x*512 + tid] *= g_invStok[t];
    __shared__ float Us[9][512];
    __shared__ float cs[9];
    #pragma unroll
    for (int k = 0; k < 9; k++) Us[k][tid] = g_U[(size_t)(t*9 + k)*D + tid];
    if (tid < 9) cs[tid] = g_c[t*9 + tid];
    __syncthreads();
    int i0 = blockIdx.x * 8;
    #pragma unroll
    for (int ii = 0; ii < 8; ii++) {
        int i = i0 + ii;
        float a = 0.f;
        #pragma unroll
        for (int k = 0; k < 9; k++) a = fmaf(cs[k]*Us[k][i], Us[k][tid], a);
        out_rho[((size_t)t*D + i)*D + tid] = a;
    }
}

// ---------------- launch ----------------
extern "C" void kernel_launch(void* const* d_in, const int* in_sizes, int n_in,
                              void* d_out, int out_size) {
    (void)in_sizes; (void)n_in; (void)out_size;
    const int*   tokens = (const int*)d_in[0];
    const float* E      = (const float*)d_in[1];
    const float* Ws     = (const float*)d_in[2];
    const float* mt     = (const float*)d_in[3];
    const float* mdb    = (const float*)d_in[4];
    const float* ns     = (const float*)d_in[5];

    float* out     = (float*)d_out;
    float* out_tok = out;                         // [4, 32768]
    float* out_rho = out_tok + T*VOCAB;           // [4, 512, 512]
    float* out_w   = out_rho + (size_t)T*D*D;     // [4, 3]
    float* out_S   = out_w + T*NF;                // [4]
    float* out_H   = out_S + T;                   // [4]
    float* out_F   = out_H + T;                   // [4]
    float* out_d   = out_F + T;                   // [4, 3, 32768]

    k_phase1<<<P1_BLOCKS, D>>>(tokens, E, Ws, mdb, ns);
    k_P<<<dim3(128, 2), 128>>>(E);
    k_meta<<<T, 512>>>(out_w, out_S, mt);
    k_token<<<dim3(64, T), 512>>>(out_tok, out_d);
    k_scal<<<T, 32>>>(out_H, out_F);
    k_rho<<<dim3(64, T), 512>>>(out_rho, out_tok);
}

// round 4
// speedup vs baseline: 1.3580x; 1.2448x over previous
#include <cuda_runtime.h>
#include <math.h>

#define VOCAB 32768
#define D 512
#define NB 3
#define NF 3
#define T 4
#define NJ 36   // T*NF*NB
#define P1_BLOCKS 72
#define JAC_SWEEPS 8

// ---------------- scratch (device globals; no allocation) ----------------
__device__ float g_xin[NF*D];
__device__ float g_part[NF*NB*8*D];
__device__ float g_U[NJ*D];          // [t][f][n][d], j = t*9+f*3+n
__device__ float g_w[NJ];            // bubble weights [t][f][n]
__device__ float g_Z[T*NF*VOCAB];    // zf = born(rho_f) logits
__device__ float g_red5[T*128*12];
__device__ float g_c[NJ];            // meta coeffs c = weights_f * w_fn
__device__ float g_wt[T*NF];         // meta foam weights
__device__ float g_invSf[T*NF];
__device__ float g_Srho[T];
__device__ float g_red7[T*16*2];
__device__ unsigned g_bar_count;     // zero-init; self-resetting
__device__ unsigned g_bar_epoch;     // monotonic across replays

// Brent-Luk round-robin: round r pairs (a,b), a<b, (a+b)%9==r (4 disjoint pairs)
__constant__ int c_pairs[9][4][2] = {
    {{1,8},{2,7},{3,6},{4,5}},
    {{0,1},{2,8},{3,7},{4,6}},
    {{0,2},{3,8},{4,7},{5,6}},
    {{0,3},{1,2},{4,8},{5,7}},
    {{0,4},{1,3},{5,8},{6,7}},
    {{0,5},{1,4},{2,3},{6,8}},
    {{0,6},{1,5},{2,4},{7,8}},
    {{0,7},{1,6},{2,5},{3,4}},
    {{0,8},{1,7},{2,6},{3,5}},
};

// ---------------- helpers ----------------
__device__ __forceinline__ float blockReduceSum512(float v, float* sh) {
    #pragma unroll
    for (int o = 16; o > 0; o >>= 1) v += __shfl_down_sync(0xffffffffu, v, o);
    int lane = threadIdx.x & 31, wid = threadIdx.x >> 5;
    if (lane == 0) sh[wid] = v;
    __syncthreads();
    float r;
    if (wid == 0) {
        r = (lane < 16) ? sh[lane] : 0.f;
        #pragma unroll
        for (int o = 8; o > 0; o >>= 1) r += __shfl_down_sync(0xffffffffu, r, o);
        if (lane == 0) sh[0] = r;
    }
    __syncthreads();
    r = sh[0];
    __syncthreads();
    return r;
}

__device__ __forceinline__ void gridSyncAll() {
    __threadfence();
    __syncthreads();
    if (threadIdx.x == 0) {
        unsigned e0 = *(volatile unsigned*)&g_bar_epoch;
        unsigned my = atomicAdd(&g_bar_count, 1u);
        if (my == P1_BLOCKS - 1u) {
            g_bar_count = 0u;
            __threadfence();
            atomicAdd(&g_bar_epoch, 1u);
        } else {
            while (*(volatile unsigned*)&g_bar_epoch == e0) { __nanosleep(64); }
        }
    }
    __syncthreads();
}

__device__ __forceinline__ void fma2(unsigned long long& d,
                                     unsigned long long a, unsigned long long b) {
    asm("fma.rn.f32x2 %0, %1, %2, %0;" : "+l"(d) : "l"(a), "l"(b));
}
__device__ __forceinline__ void unpack2(float& lo, float& hi, unsigned long long v) {
    asm("mov.b64 {%0, %1}, %2;" : "=f"(lo), "=f"(hi) : "l"(v));
}

// ---------------- phase 1: entire foam recurrence, ONE kernel ----------------
__global__ void __launch_bounds__(512) k_phase1(
        const int* __restrict__ tokens, const float* __restrict__ E,
        const float* __restrict__ Ws, const float* __restrict__ mdb,
        const float* __restrict__ nsens) {
    int b = blockIdx.x;
    int m = b >> 3, c = b & 7;
    int e = threadIdx.x;
    __shared__ float xs[64];
    __shared__ float sh[32];
    __shared__ float bcast[8];

    float w[64];
    const float* Wp = Ws + ((size_t)m*D + c*64)*D + e;
    #pragma unroll
    for (int i = 0; i < 64; i++) w[i] = Wp[(size_t)i*D];

    float mem0 = 0.f, mem1 = 0.f, mem2 = 0.f;
    float decay = 0.f;
    float sens = fabsf(nsens[0]);
    float mdb0 = mdb[0];

    for (int t = 0; t < T; t++) {
        if (e < 64) {
            xs[e] = (t == 0) ? E[(size_t)tokens[0]*D + c*64 + e]
                             : g_xin[(m/NB)*D + c*64 + e];
        }
        __syncthreads();
        float acc = 0.f;
        #pragma unroll
        for (int i = 0; i < 64; i++) acc = fmaf(xs[i], w[i], acc);
        g_part[(m*8 + c)*D + e] = acc;
        __syncthreads();
        gridSyncAll();

        if (b < NF) {
            int f = b;
            if (t == 0) {
                float a = mdb0 - sens;
                decay = 1.f / (1.f + expf(-a));
            }
            float s0 = 0.f, s1 = 0.f, s2 = 0.f;
            #pragma unroll
            for (int cc = 0; cc < 8; cc++) {
                s0 += g_part[((f*NB + 0)*8 + cc)*D + e];
                s1 += g_part[((f*NB + 1)*8 + cc)*D + e];
                s2 += g_part[((f*NB + 2)*8 + cc)*D + e];
            }
            #pragma unroll
            for (int it = 0; it < 3; it++) {
                float mn = (s0 + s1 + s2) * (1.0f/3.0f);
                s0 += 0.3f * (mn - s0);
                s1 += 0.3f * (mn - s1);
                s2 += 0.3f * (mn - s2);
            }
            float nsq0 = blockReduceSum512(s0*s0, sh);
            float nsq1 = blockReduceSum512(s1*s1, sh);
            float nsq2 = blockReduceSum512(s2*s2, sh);
            if (e == 0) {
                float nr[3] = {sqrtf(nsq0), sqrtf(nsq1), sqrtf(nsq2)};
                float mx = fmaxf(fmaxf(2.f*nr[0], 2.f*nr[1]), 2.f*nr[2]);
                float ex[3], se = 0.f;
                #pragma unroll
                for (int n = 0; n < 3; n++) { ex[n] = expf(2.f*nr[n] - mx); se += ex[n]; }
                #pragma unroll
                for (int n = 0; n < 3; n++) {
                    g_w[(t*NF + f)*NB + n] = ex[n] / se;
                    bcast[n] = 1.f / (nr[n] + 1e-10f);
                }
            }
            __syncthreads();
            g_U[((t*NF + f)*NB + 0)*D + e] = s0 * bcast[0];
            g_U[((t*NF + f)*NB + 1)*D + e] = s1 * bcast[1];
            g_U[((t*NF + f)*NB + 2)*D + e] = s2 * bcast[2];
            mem0 = decay*mem0 + (1.f - decay)*s0;
            mem1 = decay*mem1 + (1.f - decay)*s1;
            mem2 = decay*mem2 + (1.f - decay)*s2;
            if (t < T-1) {
                float x = E[(size_t)tokens[t+1]*D + e];
                float mm = (mem0 + mem1 + mem2) * (1.0f/3.0f);
                float mmsq = blockReduceSum512(mm*mm, sh);
                float dot  = blockReduceSum512(x*mm, sh);
                float xsq  = blockReduceSum512(x*x, sh);
                if (e == 0) {
                    float mn = sqrtf(mmsq) + 1e-10f;
                    float xn = sqrtf(xsq) + 1e-10f;
                    float nov = (mn > 1e-8f) ? (1.f - dot/(xn*mn)) : 1.f;
                    float a = mdb0 - sens * nov;
                    bcast[4] = 1.f / (1.f + expf(-a));
                }
                __syncthreads();
                decay = bcast[4];
                g_xin[f*D + e] = x + decay*mm;
            }
        }
        if (t < T-1) gridSyncAll();
    }
}

// ---------------- phase 2: fused P = E@U^T + born logits z + partials ----------------
__global__ void __launch_bounds__(128) k_P(const float* __restrict__ E) {
    __shared__ float Es[16][258];
    __shared__ float2 Us2[16][18];
    __shared__ float wsh[18];
    __shared__ float wred[4][24];
    int tid = threadIdx.x;
    int v0 = blockIdx.x * 256;
    int y = blockIdx.y;
    int jbase = y * 18;
    if (tid < 18) wsh[tid] = g_w[jbase + tid];

    unsigned long long acc[18];
    #pragma unroll
    for (int j = 0; j < 18; j++) acc[j] = 0ull;

    for (int c = 0; c < 32; c++) {
        int db = c * 16;
        __syncthreads();
        #pragma unroll
        for (int it = 0; it < 8; it++) {
            int flat = it*128 + tid;
            int vl = flat >> 2, f4 = flat & 3;
            float4 ev4 = *(const float4*)(E + (size_t)(v0+vl)*D + db + f4*4);
            Es[f4*4+0][vl] = ev4.x;
            Es[f4*4+1][vl] = ev4.y;
            Es[f4*4+2][vl] = ev4.z;
            Es[f4*4+3][vl] = ev4.w;
        }
        #pragma unroll
        for (int flat = tid; flat < 16*18; flat += 128) {
            int dd = flat / 18, jj = flat - dd*18;
            float u = g_U[(size_t)(jbase+jj)*D + db + dd];
            Us2[dd][jj] = make_float2(u, u);
        }
        __syncthreads();
        #pragma unroll
        for (int dd = 0; dd < 16; dd++) {
            unsigned long long ev = *(const unsigned long long*)&Es[dd][tid*2];
            #pragma unroll
            for (int jj = 0; jj < 18; jj++) {
                unsigned long long u2 = *(const unsigned long long*)&Us2[dd][jj];
                fma2(acc[jj], ev, u2);
            }
        }
    }

    int lane = tid & 31, wid = tid >> 5;
    #pragma unroll
    for (int tt = 0; tt < 2; tt++) {
        int t = 2*y + tt;
        float vals[12];
        float ef0[3], ef1[3];
        #pragma unroll
        for (int f = 0; f < 3; f++) {
            float z0 = 0.f, z1 = 0.f;
            #pragma unroll
            for (int n = 0; n < 3; n++) {
                int jj = tt*9 + f*3 + n;
                float p0, p1;
                unpack2(p0, p1, acc[jj]);
                float w = wsh[jj];
                z0 = fmaf(w*p0, p0, z0);
                z1 = fmaf(w*p1, p1, z1);
            }
            float e0 = expf(z0), e1 = expf(z1);
            ef0[f] = e0; ef1[f] = e1;
            size_t base = ((size_t)(t*3+f))*VOCAB + v0 + 2*tid;
            *(float2*)&g_Z[base] = make_float2(z0, z1);
            vals[f]   = e0 + e1;
            vals[3+f] = e0*z0 + e1*z1;
        }
        vals[6]  = ef0[0]*ef0[0] + ef1[0]*ef1[0];
        vals[7]  = ef0[0]*ef0[1] + ef1[0]*ef1[1];
        vals[8]  = ef0[0]*ef0[2] + ef1[0]*ef1[2];
        vals[9]  = ef0[1]*ef0[1] + ef1[1]*ef1[1];
        vals[10] = ef0[1]*ef0[2] + ef1[1]*ef1[2];
        vals[11] = ef0[2]*ef0[2] + ef1[2]*ef1[2];
        #pragma unroll
        for (int k = 0; k < 12; k++) {
            #pragma unroll
            for (int o = 16; o > 0; o >>= 1)
                vals[k] += __shfl_down_sync(0xffffffffu, vals[k], o);
        }
        if (lane == 0) {
            #pragma unroll
            for (int k = 0; k < 12; k++) wred[wid][tt*12 + k] = vals[k];
        }
    }
    __syncthreads();
    if (tid < 24) {
        int tt = tid / 12, k = tid % 12;
        int t = 2*y + tt;
        float s = wred[0][tid] + wred[1][tid] + wred[2][tid] + wred[3][tid];
        g_red5[(t*128 + blockIdx.x)*12 + k] = s;
    }
}

// ---------------- meta weights + warp-parallel 9x9 Jacobi ----------------
__global__ void k_meta(float* __restrict__ out_w, float* __restrict__ out_S,
                       const float* __restrict__ mt) {
    int t = blockIdx.x;
    int tid = threadIdx.x;
    __shared__ float red[12];
    __shared__ float gram[45];
    __shared__ float As[81];
    __shared__ float csh[4], ssh[4];
    if (tid < 12) {
        float s = 0.f;
        for (int b = 0; b < 128; b++) s += g_red5[(t*128 + b)*12 + tid];
        red[tid] = s;
    }
    int w = tid >> 5, lane = tid & 31;
    for (int pr = w; pr < 45; pr += 16) {
        int i = 0, rem = pr;
        while (rem > i) { rem -= (i + 1); i++; }
        int j = rem;
        float s = 0.f;
        const float* ui = g_U + (size_t)(t*9 + i)*D;
        const float* uj = g_U + (size_t)(t*9 + j)*D;
        for (int e = lane; e < D; e += 32) s += ui[e]*uj[e];
        #pragma unroll
        for (int o = 16; o > 0; o >>= 1) s += __shfl_down_sync(0xffffffffu, s, o);
        if (lane == 0) gram[pr] = s;
    }
    __syncthreads();
    if (tid == 0) {
        const float MAXENT = logf(32768.0f);
        float S[3]  = { red[0], red[1], red[2] };
        float Tm[3] = { red[3], red[4], red[5] };
        float G00 = red[6], G01 = red[7], G02 = red[8];
        float G11 = red[9], G12 = red[10], G22 = red[11];
        float H[3], conc[3], np[3];
        #pragma unroll
        for (int f = 0; f < 3; f++) {
            H[f] = logf(S[f]) - Tm[f]/S[f];
            conc[f] = 1.f - H[f]/MAXENT;
        }
        np[0] = sqrtf(G00)/S[0] + 1e-10f;
        np[1] = sqrtf(G11)/S[1] + 1e-10f;
        np[2] = sqrtf(G22)/S[2] + 1e-10f;
        float A01 = (G01/(S[0]*S[1]))/(np[0]*np[1]);
        float A02 = (G02/(S[0]*S[2]))/(np[0]*np[2]);
        float A12 = (G12/(S[1]*S[2]))/(np[1]*np[2]);
        float agree[3] = { 0.5f*(A01+A02), 0.5f*(A01+A12), 0.5f*(A02+A12) };
        float temp = fmaxf(fabsf(mt[0]), 0.01f);
        float l[3], mx = -1e30f;
        #pragma unroll
        for (int f = 0; f < 3; f++) { l[f] = conc[f]*agree[f]/temp; mx = fmaxf(mx, l[f]); }
        float ex[3], se = 0.f;
        #pragma unroll
        for (int f = 0; f < 3; f++) { ex[f] = expf(l[f]-mx); se += ex[f]; }
        float c9[9];
        #pragma unroll
        for (int f = 0; f < 3; f++) {
            float wt = ex[f]/se;
            out_w[t*3 + f] = wt;
            g_wt[t*3 + f] = wt;
            g_invSf[t*3 + f] = 1.f/S[f];
            #pragma unroll
            for (int n = 0; n < 3; n++) {
                c9[f*3+n] = wt * g_w[(t*3+f)*3 + n];
                g_c[t*9 + f*3 + n] = c9[f*3+n];
            }
        }
        for (int i = 0; i < 9; i++)
            for (int j = 0; j < 9; j++) {
                int a = i > j ? i : j, bb = i > j ? j : i;
                As[i*9+j] = sqrtf(c9[i]*c9[j]) * gram[a*(a+1)/2 + bb];
            }
    }
    __syncthreads();

    // warp-parallel cyclic Jacobi: 4 disjoint rotations per round, A <- J^T A J
    if (w == 0) {
        for (int round = 0; round < 9*JAC_SWEEPS; round++) {
            int r = round % 9;
            if (lane < 4) {
                int p = c_pairs[r][lane][0], q = c_pairs[r][lane][1];
                float apq = As[p*9+q];
                float cc = 1.f, ss = 0.f;
                if (fabsf(apq) > 1e-20f) {
                    float theta = (As[q*9+q] - As[p*9+p]) / (2.f*apq);
                    float tt = copysignf(1.f, theta) /
                               (fabsf(theta) + sqrtf(theta*theta + 1.f));
                    cc = rsqrtf(tt*tt + 1.f);
                    ss = tt*cc;
                }
                csh[lane] = cc; ssh[lane] = ss;
            }
            __syncwarp();
            // column pass: A <- A * J   (items: i in 0..8, k in 0..3)
            {
                int L = lane;
                int k = L & 3, i = L >> 2;
                int p = c_pairs[r][k][0], q = c_pairs[r][k][1];
                float cc = csh[k], ss = ssh[k];
                float aip = As[i*9+p], aiq = As[i*9+q];
                As[i*9+p] = cc*aip - ss*aiq;
                As[i*9+q] = ss*aip + cc*aiq;
                if (lane < 4) {
                    int k2 = lane, i2 = 8;
                    int p2 = c_pairs[r][k2][0], q2 = c_pairs[r][k2][1];
                    float c2 = csh[k2], s2 = ssh[k2];
                    float a1 = As[i2*9+p2], a2 = As[i2*9+q2];
                    As[i2*9+p2] = c2*a1 - s2*a2;
                    As[i2*9+q2] = s2*a1 + c2*a2;
                }
            }
            __syncwarp();
            // row pass: A <- J^T * A   (items: j in 0..8, k in 0..3)
            {
                int L = lane;
                int k = L & 3, j = L >> 2;
                int p = c_pairs[r][k][0], q = c_pairs[r][k][1];
                float cc = csh[k], ss = ssh[k];
                float apj = As[p*9+j], aqj = As[q*9+j];
                As[p*9+j] = cc*apj - ss*aqj;
                As[q*9+j] = ss*apj + cc*aqj;
                if (lane < 4) {
                    int k2 = lane, j2 = 8;
                    int p2 = c_pairs[r][k2][0], q2 = c_pairs[r][k2][1];
                    float c2 = csh[k2], s2 = ssh[k2];
                    float a1 = As[p2*9+j2], a2 = As[q2*9+j2];
                    As[p2*9+j2] = c2*a1 - s2*a2;
                    As[q2*9+j2] = s2*a1 + c2*a2;
                }
            }
            __syncwarp();
        }
    }
    __syncthreads();
    if (tid == 0) {
        float lam[9], sum = 503.0f * 1e-12f;
        for (int i = 0; i < 9; i++) { lam[i] = fmaxf(As[i*9+i], 1e-12f); sum += lam[i]; }
        float inv = 1.f/sum, Sr = 0.f;
        for (int i = 0; i < 9; i++) {
            float pp = lam[i]*inv;
            Sr -= pp * fmaxf(logf(pp), -100.f);
        }
        float pz = 1e-12f*inv;
        Sr -= 503.f * pz * fmaxf(logf(pz), -100.f);
        out_S[t] = Sr;
        g_Srho[t] = Sr;
    }
}

// ---------------- token logits (4 v/thread) + per-foam dist writes ----------------
__global__ void __launch_bounds__(512) k_token(float* __restrict__ out_tok,
                                               float* __restrict__ out_d) {
    int t = blockIdx.y;
    int v = blockIdx.x * 2048 + threadIdx.x * 4;
    int lane = threadIdx.x & 31, wid = threadIdx.x >> 5;
    __shared__ float sh6[6];
    __shared__ float wred[16*2];
    if (threadIdx.x < 3) {
        sh6[threadIdx.x]   = g_wt[t*3 + threadIdx.x];
        sh6[3+threadIdx.x] = g_invSf[t*3 + threadIdx.x];
    }
    __syncthreads();
    float z[4] = {0.f, 0.f, 0.f, 0.f};
    #pragma unroll
    for (int f = 0; f < 3; f++) {
        size_t idx = ((size_t)(t*3+f))*VOCAB + v;
        float4 zf = *(const float4*)&g_Z[idx];
        float wf = sh6[f], isf = sh6[3+f];
        z[0] = fmaf(wf, zf.x, z[0]);
        z[1] = fmaf(wf, zf.y, z[1]);
        z[2] = fmaf(wf, zf.z, z[2]);
        z[3] = fmaf(wf, zf.w, z[3]);
        float4 dv = make_float4(expf(zf.x)*isf, expf(zf.y)*isf,
                                expf(zf.z)*isf, expf(zf.w)*isf);
        *(float4*)&out_d[idx] = dv;
    }
    float e0 = expf(z[0]), e1 = expf(z[1]), e2 = expf(z[2]), e3 = expf(z[3]);
    *(float4*)&out_tok[(size_t)t*VOCAB + v] = make_float4(e0, e1, e2, e3);
    float v0 = e0 + e1 + e2 + e3;
    float v1 = e0*z[0] + e1*z[1] + e2*z[2] + e3*z[3];
    #pragma unroll
    for (int o = 16; o > 0; o >>= 1) {
        v0 += __shfl_down_sync(0xffffffffu, v0, o);
        v1 += __shfl_down_sync(0xffffffffu, v1, o);
    }
    if (lane == 0) { wred[wid*2] = v0; wred[wid*2+1] = v1; }
    __syncthreads();
    if (threadIdx.x < 2) {
        float s = 0.f;
        #pragma unroll
        for (int w2 = 0; w2 < 16; w2++) s += wred[w2*2 + threadIdx.x];
        g_red7[(t*16 + blockIdx.x)*2 + threadIdx.x] = s;
    }
}

// ---------------- rho_meta (rank-9) + H/F scalars + token prob scaling ----------------
__global__ void __launch_bounds__(512) k_rho(float* __restrict__ out_rho,
                                             float* __restrict__ out_tok,
                                             float* __restrict__ out_H,
                                             float* __restrict__ out_F) {
    int t = blockIdx.y;
    int tid = threadIdx.x;
    __shared__ float sred[2];
    __shared__ float sInv;
    __shared__ float Us[9][512];
    __shared__ float cs[9];
    if (tid < 32) {
        float val = 0.f;
        if (tid < 16)      val = g_red7[(t*16 + tid)*2 + 0];
        else               val = g_red7[(t*16 + (tid-16))*2 + 1];
        #pragma unroll
        for (int o = 8; o > 0; o >>= 1) val += __shfl_down_sync(0xffffffffu, val, o, 16);
        if (tid == 0)  sred[0] = val;
        if (tid == 16) sred[1] = val;
    }
    #pragma unroll
    for (int k = 0; k < 9; k++) Us[k][tid] = g_U[(size_t)(t*9 + k)*D + tid];
    if (tid < 9) cs[tid] = g_c[t*9 + tid];
    __syncthreads();
    if (tid == 0) {
        float S = sred[0], Tm = sred[1];
        float H = logf(S) - Tm/S;
        if (blockIdx.x == 0) {
            out_H[t] = H;
            out_F[t] = H - g_Srho[t];
        }
        sInv = 1.f/S;
    }
    __syncthreads();
    out_tok[(size_t)t*VOCAB + blockIdx.x*512 + tid] *= sInv;
    int i0 = blockIdx.x * 8;
    #pragma unroll
    for (int ii = 0; ii < 8; ii++) {
        int i = i0 + ii;
        float a = 0.f;
        #pragma unroll
        for (int k = 0; k < 9; k++) a = fmaf(cs[k]*Us[k][i], Us[k][tid], a);
        out_rho[((size_t)t*D + i)*D + tid] = a;
    }
}

// ---------------- launch ----------------
extern "C" void kernel_launch(void* const* d_in, const int* in_sizes, int n_in,
                              void* d_out, int out_size) {
    (void)in_sizes; (void)n_in; (void)out_size;
    const int*   tokens = (const int*)d_in[0];
    const float* E      = (const float*)d_in[1];
    const float* Ws     = (const float*)d_in[2];
    const float* mt     = (const float*)d_in[3];
    const float* mdb    = (const float*)d_in[4];
    const float* ns     = (const float*)d_in[5];

    float* out     = (float*)d_out;
    float* out_tok = out;                         // [4, 32768]
    float* out_rho = out_tok + T*VOCAB;           // [4, 512, 512]
    float* out_w   = out_rho + (size_t)T*D*D;     // [4, 3]
    float* out_S   = out_w + T*NF;                // [4]
    float* out_H   = out_S + T;                   // [4]
    float* out_F   = out_H + T;                   // [4]
    float* out_d   = out_F + T;                   // [4, 3, 32768]

    k_phase1<<<P1_BLOCKS, D>>>(tokens, E, Ws, mdb, ns);
    k_P<<<dim3(128, 2), 128>>>(E);
    k_meta<<<T, 512>>>(out_w, out_S, mt);
    k_token<<<dim3(16, T), 512>>>(out_tok, out_d);
    k_rho<<<dim3(64, T), 512>>>(out_rho, out_tok, out_H, out_F);
}

// round 6
// speedup vs baseline: 1.4672x; 1.0805x over previous
#include <cuda_runtime.h>
#include <math.h>

#define VOCAB 32768
#define D 512
#define NB 3
#define NF 3
#define T 4
#define NJ 36   // T*NF*NB
#define P1_BLOCKS 72
#define JAC_SWEEPS 8

// ---------------- scratch (device globals; no allocation) ----------------
__device__ float g_part[2*NF*NB*8*D];   // double-buffered by t-parity
__device__ float g_U[NJ*D];             // [t][f][n][d], j = t*9+f*3+n
__device__ float g_w[NJ];               // bubble weights [t][f][n]
__device__ float g_Z[T*NF*VOCAB];       // zf = born(rho_f) logits
__device__ float g_red5[T*128*12];
__device__ float g_c[NJ];               // meta coeffs c = weights_f * w_fn
__device__ float g_wt[T*NF];            // meta foam weights
__device__ float g_invSf[T*NF];
__device__ float g_Srho[T];
__device__ float g_red7[T*32*2];
__device__ unsigned g_bar_count;        // zero-init; self-resetting
__device__ unsigned g_bar_epoch;        // monotonic across replays

// Brent-Luk round-robin pairs for 9x9 Jacobi
__constant__ int c_pairs[9][4][2] = {
    {{1,8},{2,7},{3,6},{4,5}},
    {{0,1},{2,8},{3,7},{4,6}},
    {{0,2},{3,8},{4,7},{5,6}},
    {{0,3},{1,2},{4,8},{5,7}},
    {{0,4},{1,3},{5,8},{6,7}},
    {{0,5},{1,4},{2,3},{6,8}},
    {{0,6},{1,5},{2,4},{7,8}},
    {{0,7},{1,6},{2,5},{3,4}},
    {{0,8},{1,7},{2,6},{3,5}},
};

// ---------------- helpers ----------------
__device__ __forceinline__ void gridSyncAll() {
    __threadfence();
    __syncthreads();
    if (threadIdx.x == 0) {
        unsigned e0 = *(volatile unsigned*)&g_bar_epoch;
        unsigned my = atomicAdd(&g_bar_count, 1u);
        if (my == P1_BLOCKS - 1u) {
            g_bar_count = 0u;
            __threadfence();
            atomicAdd(&g_bar_epoch, 1u);
        } else {
            while (*(volatile unsigned*)&g_bar_epoch == e0) { __nanosleep(64); }
        }
    }
    __syncthreads();
}

// batched 3-value block reduction (512 threads); results into res[3] (shared)
__device__ __forceinline__ void blockReduce3(float a, float b, float c,
                                             float* sh48, float* res) {
    #pragma unroll
    for (int o = 16; o > 0; o >>= 1) {
        a += __shfl_down_sync(0xffffffffu, a, o);
        b += __shfl_down_sync(0xffffffffu, b, o);
        c += __shfl_down_sync(0xffffffffu, c, o);
    }
    int lane = threadIdx.x & 31, wid = threadIdx.x >> 5;
    if (lane == 0) { sh48[wid*3+0] = a; sh48[wid*3+1] = b; sh48[wid*3+2] = c; }
    __syncthreads();
    if (threadIdx.x < 3) {
        float s = 0.f;
        #pragma unroll
        for (int i = 0; i < 16; i++) s += sh48[i*3 + threadIdx.x];
        res[threadIdx.x] = s;
    }
    __syncthreads();
}

__device__ __forceinline__ void fma2(unsigned long long& d,
                                     unsigned long long a, unsigned long long b) {
    asm("fma.rn.f32x2 %0, %1, %2, %0;" : "+l"(d) : "l"(a), "l"(b));
}
__device__ __forceinline__ void unpack2(float& lo, float& hi, unsigned long long v) {
    asm("mov.b64 {%0, %1}, %2;" : "=f"(lo), "=f"(hi) : "l"(v));
}

// ---------------- phase 1: entire foam recurrence, ONE kernel, 1 barrier/step ----------------
__global__ void __launch_bounds__(512) k_phase1(
        const int* __restrict__ tokens, const float* __restrict__ E,
        const float* __restrict__ Ws, const float* __restrict__ mdb,
        const float* __restrict__ nsens) {
    int b = blockIdx.x;
    int m = b >> 3, c = b & 7, f = m / NB;
    int e = threadIdx.x;
    bool writer = ((b % 24) == 0);     // blocks 0,24,48 own f=0,1,2 outputs
    __shared__ float xs[64];
    __shared__ float sh48[48];
    __shared__ float res[3];
    __shared__ float bcast[8];

    float w[64];
    const float* Wp = Ws + ((size_t)m*D + c*64)*D + e;
    #pragma unroll
    for (int i = 0; i < 64; i++) w[i] = Wp[(size_t)i*D];

    float mem0 = 0.f, mem1 = 0.f, mem2 = 0.f;
    float decay = 0.f;
    float sens = fabsf(nsens[0]);
    float mdb0 = mdb[0];
    float xin_e = E[(size_t)tokens[0]*D + e];

    for (int t = 0; t < T; t++) {
        if ((e >> 6) == c) xs[e & 63] = xin_e;
        __syncthreads();
        float acc = 0.f;
        #pragma unroll
        for (int i = 0; i < 64; i++) acc = fmaf(xs[i], w[i], acc);
        int buf = (t & 1) * (NF*NB*8*D);
        g_part[buf + (m*8 + c)*D + e] = acc;
        __syncthreads();
        gridSyncAll();

        if (t == 0) {
            float a = mdb0 - sens;
            decay = 1.f / (1.f + expf(-a));
        }
        float s0 = 0.f, s1 = 0.f, s2 = 0.f;
        #pragma unroll
        for (int cc = 0; cc < 8; cc++) {
            s0 += g_part[buf + ((f*NB + 0)*8 + cc)*D + e];
            s1 += g_part[buf + ((f*NB + 1)*8 + cc)*D + e];
            s2 += g_part[buf + ((f*NB + 2)*8 + cc)*D + e];
        }
        #pragma unroll
        for (int it = 0; it < 3; it++) {
            float mn = (s0 + s1 + s2) * (1.0f/3.0f);
            s0 += 0.3f * (mn - s0);
            s1 += 0.3f * (mn - s1);
            s2 += 0.3f * (mn - s2);
        }
        if (writer) {
            blockReduce3(s0*s0, s1*s1, s2*s2, sh48, res);
            if (e == 0) {
                float nr[3] = {sqrtf(res[0]), sqrtf(res[1]), sqrtf(res[2])};
                float mx = fmaxf(fmaxf(2.f*nr[0], 2.f*nr[1]), 2.f*nr[2]);
                float ex[3], se = 0.f;
                #pragma unroll
                for (int n = 0; n < 3; n++) { ex[n] = expf(2.f*nr[n] - mx); se += ex[n]; }
                #pragma unroll
                for (int n = 0; n < 3; n++) {
                    g_w[(t*NF + f)*NB + n] = ex[n] / se;
                    bcast[n] = 1.f / (nr[n] + 1e-10f);
                }
            }
            __syncthreads();
            g_U[((t*NF + f)*NB + 0)*D + e] = s0 * bcast[0];
            g_U[((t*NF + f)*NB + 1)*D + e] = s1 * bcast[1];
            g_U[((t*NF + f)*NB + 2)*D + e] = s2 * bcast[2];
        }
        mem0 = decay*mem0 + (1.f - decay)*s0;
        mem1 = decay*mem1 + (1.f - decay)*s1;
        mem2 = decay*mem2 + (1.f - decay)*s2;
        if (t < T-1) {
            float x = E[(size_t)tokens[t+1]*D + e];
            float mm = (mem0 + mem1 + mem2) * (1.0f/3.0f);
            blockReduce3(mm*mm, x*mm, x*x, sh48, res);
            if (e == 0) {
                float mn = sqrtf(res[0]) + 1e-10f;
                float xn = sqrtf(res[2]) + 1e-10f;
                float nov = (mn > 1e-8f) ? (1.f - res[1]/(xn*mn)) : 1.f;
                float a = mdb0 - sens * nov;
                bcast[4] = 1.f / (1.f + expf(-a));
            }
            __syncthreads();
            decay = bcast[4];
            xin_e = x + decay*mm;
        }
    }
}

// ---------------- phase 2: fused P = E@U^T + born logits z + partials ----------------
// 128 blocks x 256 threads. Block handles 256 v, ALL 36 columns (E read ONCE).
// Warp w: t = w>>1, vh = w&1. Each warp covers 128 v (vt=4) via two f32x2 banks:
//   bank A at v0 + vh*128 + lane*2, bank B at +64.
__global__ void __launch_bounds__(256) k_P(const float* __restrict__ E) {
    __shared__ float Es[16][258];
    __shared__ float2 Us2[16][36];
    __shared__ float wsh[36];
    __shared__ float wred[8][12];
    int tid = threadIdx.x;
    int w = tid >> 5, lane = tid & 31;
    int t = w >> 1, vh = w & 1;
    int v0 = blockIdx.x * 256;
    if (tid < 36) wsh[tid] = g_w[tid];

    unsigned long long accA[9], accB[9];
    #pragma unroll
    for (int j = 0; j < 9; j++) { accA[j] = 0ull; accB[j] = 0ull; }

    int vbase = vh*128 + lane*2;   // bank A; bank B = vbase + 64

    for (int c = 0; c < 32; c++) {
        int db = c * 16;
        __syncthreads();
        #pragma unroll
        for (int it = 0; it < 4; it++) {
            int flat = it*256 + tid;
            int vl = flat >> 2, f4 = flat & 3;
            float4 ev4 = *(const float4*)(E + (size_t)(v0+vl)*D + db + f4*4);
            Es[f4*4+0][vl] = ev4.x;
            Es[f4*4+1][vl] = ev4.y;
            Es[f4*4+2][vl] = ev4.z;
            Es[f4*4+3][vl] = ev4.w;
        }
        #pragma unroll
        for (int flat = tid; flat < 16*36; flat += 256) {
            int dd = flat / 36, jj = flat - dd*36;
            float u = g_U[(size_t)jj*D + db + dd];
            Us2[dd][jj] = make_float2(u, u);
        }
        __syncthreads();
        #pragma unroll
        for (int dd = 0; dd < 16; dd++) {
            unsigned long long evA = *(const unsigned long long*)&Es[dd][vbase];
            unsigned long long evB = *(const unsigned long long*)&Es[dd][vbase + 64];
            #pragma unroll
            for (int jj = 0; jj < 9; jj++) {
                unsigned long long u2 = *(const unsigned long long*)&Us2[dd][t*9+jj];
                fma2(accA[jj], evA, u2);
                fma2(accB[jj], evB, u2);
            }
        }
    }

    // epilogue: this warp owns (t, 4 v values: vbase..+1, vbase+64..+65)
    float vals[12];
    float eA0[3], eA1[3], eB0[3], eB1[3];
    #pragma unroll
    for (int f = 0; f < 3; f++) {
        float zA0 = 0.f, zA1 = 0.f, zB0 = 0.f, zB1 = 0.f;
        #pragma unroll
        for (int n = 0; n < 3; n++) {
            float pA0, pA1, pB0, pB1;
            unpack2(pA0, pA1, accA[f*3+n]);
            unpack2(pB0, pB1, accB[f*3+n]);
            float ww = wsh[t*9 + f*3 + n];
            zA0 = fmaf(ww*pA0, pA0, zA0);
            zA1 = fmaf(ww*pA1, pA1, zA1);
            zB0 = fmaf(ww*pB0, pB0, zB0);
            zB1 = fmaf(ww*pB1, pB1, zB1);
        }
        float a0 = __expf(zA0), a1 = __expf(zA1);
        float b0 = __expf(zB0), b1 = __expf(zB1);
        eA0[f] = a0; eA1[f] = a1; eB0[f] = b0; eB1[f] = b1;
        size_t base = ((size_t)(t*3+f))*VOCAB + v0 + vbase;
        *(float2*)&g_Z[base]      = make_float2(zA0, zA1);
        *(float2*)&g_Z[base + 64] = make_float2(zB0, zB1);
        vals[f]   = a0 + a1 + b0 + b1;
        vals[3+f] = a0*zA0 + a1*zA1 + b0*zB0 + b1*zB1;
    }
    vals[6]  = eA0[0]*eA0[0] + eA1[0]*eA1[0] + eB0[0]*eB0[0] + eB1[0]*eB1[0];
    vals[7]  = eA0[0]*eA0[1] + eA1[0]*eA1[1] + eB0[0]*eB0[1] + eB1[0]*eB1[1];
    vals[8]  = eA0[0]*eA0[2] + eA1[0]*eA1[2] + eB0[0]*eB0[2] + eB1[0]*eB1[2];
    vals[9]  = eA0[1]*eA0[1] + eA1[1]*eA1[1] + eB0[1]*eB0[1] + eB1[1]*eB1[1];
    vals[10] = eA0[1]*eA0[2] + eA1[1]*eA1[2] + eB0[1]*eB0[2] + eB1[1]*eB1[2];
    vals[11] = eA0[2]*eA0[2] + eA1[2]*eA1[2] + eB0[2]*eB0[2] + eB1[2]*eB1[2];
    #pragma unroll
    for (int k = 0; k < 12; k++) {
        #pragma unroll
        for (int o = 16; o > 0; o >>= 1)
            vals[k] += __shfl_down_sync(0xffffffffu, vals[k], o);
    }
    if (lane == 0) {
        #pragma unroll
        for (int k = 0; k < 12; k++) wred[w][k] = vals[k];
    }
    __syncthreads();
    if (tid < 48) {
        int t2 = tid / 12, k = tid % 12;
        g_red5[(t2*128 + blockIdx.x)*12 + k] = wred[t2*2][k] + wred[t2*2+1][k];
    }
}

// ---------------- meta weights + warp-parallel 9x9 Jacobi ----------------
__global__ void k_meta(float* __restrict__ out_w, float* __restrict__ out_S,
                       const float* __restrict__ mt) {
    int t = blockIdx.x;
    int tid = threadIdx.x;
    __shared__ float red[12];
    __shared__ float gram[45];
    __shared__ float As[81];
    __shared__ float csh[4], ssh[4];
    if (tid < 12) {
        float s = 0.f;
        for (int b = 0; b < 128; b++) s += g_red5[(t*128 + b)*12 + tid];
        red[tid] = s;
    }
    int w = tid >> 5, lane = tid & 31;
    for (int pr = w; pr < 45; pr += 16) {
        int i = 0, rem = pr;
        while (rem > i) { rem -= (i + 1); i++; }
        int j = rem;
        float s = 0.f;
        const float* ui = g_U + (size_t)(t*9 + i)*D;
        const float* uj = g_U + (size_t)(t*9 + j)*D;
        for (int e = lane; e < D; e += 32) s += ui[e]*uj[e];
        #pragma unroll
        for (int o = 16; o > 0; o >>= 1) s += __shfl_down_sync(0xffffffffu, s, o);
        if (lane == 0) gram[pr] = s;
    }
    __syncthreads();
    if (tid == 0) {
        const float MAXENT = logf(32768.0f);
        float S[3]  = { red[0], red[1], red[2] };
        float Tm[3] = { red[3], red[4], red[5] };
        float G00 = red[6], G01 = red[7], G02 = red[8];
        float G11 = red[9], G12 = red[10], G22 = red[11];
        float H[3], conc[3], np[3];
        #pragma unroll
        for (int f = 0; f < 3; f++) {
            H[f] = logf(S[f]) - Tm[f]/S[f];
            conc[f] = 1.f - H[f]/MAXENT;
        }
        np[0] = sqrtf(G00)/S[0] + 1e-10f;
        np[1] = sqrtf(G11)/S[1] + 1e-10f;
        np[2] = sqrtf(G22)/S[2] + 1e-10f;
        float A01 = (G01/(S[0]*S[1]))/(np[0]*np[1]);
        float A02 = (G02/(S[0]*S[2]))/(np[0]*np[2]);
        float A12 = (G12/(S[1]*S[2]))/(np[1]*np[2]);
        float agree[3] = { 0.5f*(A01+A02), 0.5f*(A01+A12), 0.5f*(A02+A12) };
        float temp = fmaxf(fabsf(mt[0]), 0.01f);
        float l[3], mx = -1e30f;
        #pragma unroll
        for (int f = 0; f < 3; f++) { l[f] = conc[f]*agree[f]/temp; mx = fmaxf(mx, l[f]); }
        float ex[3], se = 0.f;
        #pragma unroll
        for (int f = 0; f < 3; f++) { ex[f] = expf(l[f]-mx); se += ex[f]; }
        float c9[9];
        #pragma unroll
        for (int f = 0; f < 3; f++) {
            float wt = ex[f]/se;
            out_w[t*3 + f] = wt;
            g_wt[t*3 + f] = wt;
            g_invSf[t*3 + f] = 1.f/S[f];
            #pragma unroll
            for (int n = 0; n < 3; n++) {
                c9[f*3+n] = wt * g_w[(t*3+f)*3 + n];
                g_c[t*9 + f*3 + n] = c9[f*3+n];
            }
        }
        for (int i = 0; i < 9; i++)
            for (int j = 0; j < 9; j++) {
                int a = i > j ? i : j, bb = i > j ? j : i;
                As[i*9+j] = sqrtf(c9[i]*c9[j]) * gram[a*(a+1)/2 + bb];
            }
    }
    __syncthreads();

    if (w == 0) {
        for (int round = 0; round < 9*JAC_SWEEPS; round++) {
            int r = round % 9;
            if (lane < 4) {
                int p = c_pairs[r][lane][0], q = c_pairs[r][lane][1];
                float apq = As[p*9+q];
                float cc = 1.f, ss = 0.f;
                if (fabsf(apq) > 1e-20f) {
                    float theta = (As[q*9+q] - As[p*9+p]) / (2.f*apq);
                    float tt = copysignf(1.f, theta) /
                               (fabsf(theta) + sqrtf(theta*theta + 1.f));
                    cc = rsqrtf(tt*tt + 1.f);
                    ss = tt*cc;
                }
                csh[lane] = cc; ssh[lane] = ss;
            }
            __syncwarp();
            {
                int k = lane & 3, i = lane >> 2;
                int p = c_pairs[r][k][0], q = c_pairs[r][k][1];
                float cc = csh[k], ss = ssh[k];
                float aip = As[i*9+p], aiq = As[i*9+q];
                As[i*9+p] = cc*aip - ss*aiq;
                As[i*9+q] = ss*aip + cc*aiq;
                if (lane < 4) {
                    int p2 = c_pairs[r][lane][0], q2 = c_pairs[r][lane][1];
                    float c2 = csh[lane], s2 = ssh[lane];
                    float a1 = As[8*9+p2], a2 = As[8*9+q2];
                    As[8*9+p2] = c2*a1 - s2*a2;
                    As[8*9+q2] = s2*a1 + c2*a2;
                }
            }
            __syncwarp();
            {
                int k = lane & 3, j = lane >> 2;
                int p = c_pairs[r][k][0], q = c_pairs[r][k][1];
                float cc = csh[k], ss = ssh[k];
                float apj = As[p*9+j], aqj = As[q*9+j];
                As[p*9+j] = cc*apj - ss*aqj;
                As[q*9+j] = ss*apj + cc*aqj;
                if (lane < 4) {
                    int p2 = c_pairs[r][lane][0], q2 = c_pairs[r][lane][1];
                    float c2 = csh[lane], s2 = ssh[lane];
                    float a1 = As[p2*9+8], a2 = As[q2*9+8];
                    As[p2*9+8] = c2*a1 - s2*a2;
                    As[q2*9+8] = s2*a1 + c2*a2;
                }
            }
            __syncwarp();
        }
    }
    __syncthreads();
    if (tid == 0) {
        float lam[9], sum = 503.0f * 1e-12f;
        for (int i = 0; i < 9; i++) { lam[i] = fmaxf(As[i*9+i], 1e-12f); sum += lam[i]; }
        float inv = 1.f/sum, Sr = 0.f;
        for (int i = 0; i < 9; i++) {
            float pp = lam[i]*inv;
            Sr -= pp * fmaxf(logf(pp), -100.f);
        }
        float pz = 1e-12f*inv;
        Sr -= 503.f * pz * fmaxf(logf(pz), -100.f);
        out_S[t] = Sr;
        g_Srho[t] = Sr;
    }
}

// ---------------- token logits (2 v/thread) + per-foam dist writes ----------------
__global__ void __launch_bounds__(512) k_token(float* __restrict__ out_tok,
                                               float* __restrict__ out_d) {
    int t = blockIdx.y;
    int v = blockIdx.x * 1024 + threadIdx.x * 2;
    int lane = threadIdx.x & 31, wid = threadIdx.x >> 5;
    __shared__ float sh6[6];
    __shared__ float wred[16*2];
    if (threadIdx.x < 3) {
        sh6[threadIdx.x]   = g_wt[t*3 + threadIdx.x];
        sh6[3+threadIdx.x] = g_invSf[t*3 + threadIdx.x];
    }
    __syncthreads();
    float z0 = 0.f, z1 = 0.f;
    #pragma unroll
    for (int f = 0; f < 3; f++) {
        size_t idx = ((size_t)(t*3+f))*VOCAB + v;
        float2 zf = *(const float2*)&g_Z[idx];
        float wf = sh6[f], isf = sh6[3+f];
        z0 = fmaf(wf, zf.x, z0);
        z1 = fmaf(wf, zf.y, z1);
        *(float2*)&out_d[idx] = make_float2(__expf(zf.x)*isf, __expf(zf.y)*isf);
    }
    float e0 = __expf(z0), e1 = __expf(z1);
    *(float2*)&out_tok[(size_t)t*VOCAB + v] = make_float2(e0, e1);
    float v0 = e0 + e1;
    float v1 = e0*z0 + e1*z1;
    #pragma unroll
    for (int o = 16; o > 0; o >>= 1) {
        v0 += __shfl_down_sync(0xffffffffu, v0, o);
        v1 += __shfl_down_sync(0xffffffffu, v1, o);
    }
    if (lane == 0) { wred[wid*2] = v0; wred[wid*2+1] = v1; }
    __syncthreads();
    if (threadIdx.x < 2) {
        float s = 0.f;
        #pragma unroll
        for (int w2 = 0; w2 < 16; w2++) s += wred[w2*2 + threadIdx.x];
        g_red7[(t*32 + blockIdx.x)*2 + threadIdx.x] = s;
    }
}

// ---------------- rho_meta (rank-9) + H/F scalars + token prob scaling ----------------
__global__ void __launch_bounds__(512) k_rho(float* __restrict__ out_rho,
                                             float* __restrict__ out_tok,
                                             float* __restrict__ out_H,
                                             float* __restrict__ out_F) {
    int t = blockIdx.y;
    int tid = threadIdx.x;
    __shared__ float sred[2];
    __shared__ float sInv;
    __shared__ float Us[9][512];
    __shared__ float cs[9];
    if (tid < 64) {
        int k = tid >> 5, i = tid & 31;
        float val = g_red7[(t*32 + i)*2 + k];
        #pragma unroll
        for (int o = 16; o > 0; o >>= 1) val += __shfl_down_sync(0xffffffffu, val, o);
        if (i == 0) sred[k] = val;
    }
    #pragma unroll
    for (int k = 0; k < 9; k++) Us[k][tid] = g_U[(size_t)(t*9 + k)*D + tid];
    if (tid < 9) cs[tid] = g_c[t*9 + tid];
    __syncthreads();
    if (tid == 0) {
        float S = sred[0], Tm = sred[1];
        float H = logf(S) - Tm/S;
        if (blockIdx.x == 0) {
            out_H[t] = H;
            out_F[t] = H - g_Srho[t];
        }
        sInv = 1.f/S;
    }
    __syncthreads();
    out_tok[(size_t)t*VOCAB + blockIdx.x*512 + tid] *= sInv;
    int i0 = blockIdx.x * 8;
    #pragma unroll
    for (int ii = 0; ii < 8; ii++) {
        int i = i0 + ii;
        float a = 0.f;
        #pragma unroll
        for (int k = 0; k < 9; k++) a = fmaf(cs[k]*Us[k][i], Us[k][tid], a);
        out_rho[((size_t)t*D + i)*D + tid] = a;
    }
}

// ---------------- launch ----------------
extern "C" void kernel_launch(void* const* d_in, const int* in_sizes, int n_in,
                              void* d_out, int out_size) {
    (void)in_sizes; (void)n_in; (void)out_size;
    const int*   tokens = (const int*)d_in[0];
    const float* E      = (const float*)d_in[1];
    const float* Ws     = (const float*)d_in[2];
    const float* mt     = (const float*)d_in[3];
    const float* mdb    = (const float*)d_in[4];
    const float* ns     = (const float*)d_in[5];

    float* out     = (float*)d_out;
    float* out_tok = out;                         // [4, 32768]
    float* out_rho = out_tok + T*VOCAB;           // [4, 512, 512]
    float* out_w   = out_rho + (size_t)T*D*D;     // [4, 3]
    float* out_S   = out_w + T*NF;                // [4]
    float* out_H   = out_S + T;                   // [4]
    float* out_F   = out_H + T;                   // [4]
    float* out_d   = out_F + T;                   // [4, 3, 32768]

    k_phase1<<<P1_BLOCKS, D>>>(tokens, E, Ws, mdb, ns);
    k_P<<<128, 256>>>(E);
    k_meta<<<T, 512>>>(out_w, out_S, mt);
    k_token<<<dim3(32, T), 512>>>(out_tok, out_d);
    k_rho<<<dim3(64, T), 512>>>(out_rho, out_tok, out_H, out_F);
}